// round 14
// baseline (speedup 1.0000x reference)
#include <cuda_runtime.h>
#include <cuda_fp16.h>
#include <cstdint>

#define HIDDEN 1024
#define SLOTS 16
#define BSZ 512
#define SEGLEN 256
#define TT 16            // t-tile in fused attention
#define SCALE 0.03125f   // 1/sqrt(1024)

// ---------------- scratch (device globals; no allocation) ----------------
__device__ float  g_wo[HIDDEN * HIDDEN];                  // RNA-rounded Wo
__device__ float  g_wv[HIDDEN * HIDDEN];                  // RNA-rounded Wv
__device__ float  g_q1[SLOTS * HIDDEN];                   // exact fp32 q1
__device__ __half g_q2h[SLOTS * HIDDEN];                  // fp16 Q2
__device__ __half g_w2h[HIDDEN * HIDDEN];                 // fp16 W2 = Wo@Wv
__device__ float  g_b2[HIDDEN];
__device__ __half g_yh[(size_t)BSZ * SLOTS * HIDDEN];     // fp16 Y [b][s][d]

// ---------------- helpers ----------------
__device__ __forceinline__ float tf32r(float x) {
    uint32_t u;
    asm("cvt.rna.tf32.f32 %0, %1;" : "=r"(u) : "f"(x));
    return __uint_as_float(u);
}
__device__ __forceinline__ float4 tf32r4(float4 v) {
    return make_float4(tf32r(v.x), tf32r(v.y), tf32r(v.z), tf32r(v.w));
}
__device__ __forceinline__ uint32_t f2u(float x) { return __float_as_uint(x); }

__device__ __forceinline__ void mma8(float* c, const uint32_t* a, const uint32_t* b) {
    asm volatile(
        "mma.sync.aligned.m16n8k8.row.col.f32.tf32.tf32.f32 "
        "{%0,%1,%2,%3},{%4,%5,%6,%7},{%8,%9},{%0,%1,%2,%3};"
        : "+f"(c[0]), "+f"(c[1]), "+f"(c[2]), "+f"(c[3])
        : "r"(a[0]), "r"(a[1]), "r"(a[2]), "r"(a[3]), "r"(b[0]), "r"(b[1]));
}
__device__ __forceinline__ void mma16h(float* c, const uint32_t* a, const uint32_t* b) {
    asm volatile(
        "mma.sync.aligned.m16n8k16.row.col.f32.f16.f16.f32 "
        "{%0,%1,%2,%3},{%4,%5,%6,%7},{%8,%9},{%0,%1,%2,%3};"
        : "+f"(c[0]), "+f"(c[1]), "+f"(c[2]), "+f"(c[3])
        : "r"(a[0]), "r"(a[1]), "r"(a[2]), "r"(a[3]), "r"(b[0]), "r"(b[1]));
}
__device__ __forceinline__ void ldsm4t(uint32_t& r0, uint32_t& r1, uint32_t& r2, uint32_t& r3,
                                       uint32_t a) {
    asm volatile("ldmatrix.sync.aligned.m8n8.x4.trans.shared.b16 {%0,%1,%2,%3}, [%4];"
                 : "=r"(r0), "=r"(r1), "=r"(r2), "=r"(r3) : "r"(a));
}

__device__ __forceinline__ uint32_t smem_u32(const void* p) {
    uint32_t a;
    asm("{ .reg .u64 t; cvta.to.shared.u64 t, %1; cvt.u32.u64 %0, t; }" : "=r"(a) : "l"(p));
    return a;
}
__device__ __forceinline__ void cpasync16(uint32_t dst, const void* src) {
    asm volatile("cp.async.cg.shared.global [%0], [%1], 16;" :: "r"(dst), "l"(src));
}
#define CP_COMMIT() asm volatile("cp.async.commit_group;")
#define CP_WAIT(n)  asm volatile("cp.async.wait_group %0;" :: "n"(n))

// ---------------- batched RNA round-copy (side branch only) ----------------
__global__ void __launch_bounds__(256) k_round2(
    float* d0, const float* s0, float* d1, const float* s1) {
    const float* s = blockIdx.y ? s1 : s0;
    float* d = blockIdx.y ? d1 : d0;
    int i = blockIdx.x * 256 + threadIdx.x;
    ((float4*)d)[i] = tf32r4(((const float4*)s)[i]);
}

// ---------------- exact fp32 q-chain kernels ----------------
// k_q1: q1[s][e] = dot(A[s,:], W[e,:]) + bias[e]    (W row-major [E,K], dot over K)
// grid 64 CTAs x 256 thr; CTA handles 16 e; thread (el=tid&15, kp=tid>>4) covers 64 k.
__global__ void __launch_bounds__(256) k_q1(
    const float* __restrict__ A, const float* __restrict__ W,
    const float* __restrict__ bias, float* __restrict__ out)
{
    extern __shared__ float dsm[];
    float* as   = dsm;                  // [16][1024]
    float* part = dsm + SLOTS * HIDDEN; // [kp][s][el] = [16][16][16]
    int tid = threadIdx.x;
    for (int i = tid; i < SLOTS * HIDDEN / 4; i += 256)
        ((float4*)as)[i] = ((const float4*)A)[i];
    __syncthreads();

    int el = tid & 15, kp = tid >> 4;
    int e = blockIdx.x * 16 + el;
    float acc[SLOTS];
    #pragma unroll
    for (int s = 0; s < SLOTS; s++) acc[s] = 0.0f;
    const float* wrow = W + (long)e * HIDDEN + kp * 64;
    for (int k = 0; k < 64; k += 4) {
        float4 wv = *(const float4*)(wrow + k);
        int kk = kp * 64 + k;
        #pragma unroll
        for (int s = 0; s < SLOTS; s++) {
            acc[s] = fmaf(as[s * HIDDEN + kk],     wv.x, acc[s]);
            acc[s] = fmaf(as[s * HIDDEN + kk + 1], wv.y, acc[s]);
            acc[s] = fmaf(as[s * HIDDEN + kk + 2], wv.z, acc[s]);
            acc[s] = fmaf(as[s * HIDDEN + kk + 3], wv.w, acc[s]);
        }
    }
    #pragma unroll
    for (int s = 0; s < SLOTS; s++) part[(kp * 16 + s) * 16 + el] = acc[s];
    __syncthreads();
    int s = tid >> 4;   // reduce: thread (el, s)
    float r = 0.0f;
    #pragma unroll
    for (int k2 = 0; k2 < 16; k2++) r += part[(k2 * 16 + s) * 16 + el];
    out[(long)s * HIDDEN + e] = r + bias[e];
}

// k_q2: q2h[s][d] = fp16( dot(q1[s,:], W[:,d]) )   (W row-major [K,D], column access)
__global__ void __launch_bounds__(256) k_q2(
    const float* __restrict__ A, const float* __restrict__ W,
    __half* __restrict__ out)
{
    extern __shared__ float dsm[];
    float* as   = dsm;
    float* part = dsm + SLOTS * HIDDEN;
    int tid = threadIdx.x;
    for (int i = tid; i < SLOTS * HIDDEN / 4; i += 256)
        ((float4*)as)[i] = ((const float4*)A)[i];
    __syncthreads();

    int dl = tid & 15, kp = tid >> 4;
    int d = blockIdx.x * 16 + dl;
    float acc[SLOTS];
    #pragma unroll
    for (int s = 0; s < SLOTS; s++) acc[s] = 0.0f;
    for (int k = 0; k < 64; k++) {
        int kk = kp * 64 + k;
        float wv = W[(long)kk * HIDDEN + d];
        #pragma unroll
        for (int s = 0; s < SLOTS; s++)
            acc[s] = fmaf(as[s * HIDDEN + kk], wv, acc[s]);
    }
    #pragma unroll
    for (int s = 0; s < SLOTS; s++) part[(kp * 16 + s) * 16 + dl] = acc[s];
    __syncthreads();
    int s = tid >> 4;
    float r = 0.0f;
    #pragma unroll
    for (int k2 = 0; k2 < 16; k2++) r += part[(k2 * 16 + s) * 16 + dl];
    out[(long)s * HIDDEN + d] = __float2half_rn(r);
}

// ---------------- multi-stage cp.async tf32 GEMM (W2 only) ----------------
template <int BM, int BN, int BK, int WM, int WN, int STAGES,
          bool BT, bool BIAS, bool RNA, bool HOUT, int MINCTA>
__global__ void __launch_bounds__(WM * WN * 32, MINCTA) gemm_cpa(
    const float* __restrict__ A, const float* __restrict__ B,
    float* __restrict__ C, const float* __restrict__ bias,
    int M, int N, int K)
{
    constexpr int THREADS = WM * WN * 32;
    constexpr int LA = BK + 8;
    constexpr int LB = BN + 8;
    constexpr int ASZ = BM * LA;
    constexpr int BSZE = BT ? BN * LA : BK * LB;
    constexpr int AITER = BM * BK / 4 / THREADS;
    constexpr int BITER = BN * BK / 4 / THREADS;

    extern __shared__ float sm[];

    const int tid  = threadIdx.x;
    const int lane = tid & 31;
    const int warp = tid >> 5;
    const int r  = lane >> 2;
    const int cq = lane & 3;
    const int wm = warp / WN, wn = warp % WN;
    constexpr int WTM = BM / WM, WTN = BN / WN;
    constexpr int MI = WTM / 16, NI = WTN / 8;
    const int mW = wm * WTM, nW = wn * WTN;
    const int m0 = blockIdx.y * BM;
    const int n0 = blockIdx.x * BN;

    float acc[MI][NI][4];
    #pragma unroll
    for (int mi = 0; mi < MI; mi++)
        #pragma unroll
        for (int ni = 0; ni < NI; ni++)
            #pragma unroll
            for (int j = 0; j < 4; j++) acc[mi][ni][j] = 0.0f;

    auto issue = [&](int k0, int buf) {
        float* As = sm + buf * (ASZ + BSZE);
        float* Bs = As + ASZ;
        uint32_t ab = smem_u32(As);
        uint32_t bb = smem_u32(Bs);
        #pragma unroll
        for (int i = 0; i < AITER; i++) {
            int idx = i * THREADS + tid;
            int row = idx / (BK / 4), k4 = idx % (BK / 4);
            cpasync16(ab + (row * LA + k4 * 4) * 4,
                      A + (long)(m0 + row) * K + k0 + k4 * 4);
        }
        if constexpr (BT) {
            #pragma unroll
            for (int i = 0; i < BITER; i++) {
                int idx = i * THREADS + tid;
                int row = idx / (BK / 4), k4 = idx % (BK / 4);
                cpasync16(bb + (row * LA + k4 * 4) * 4,
                          B + (long)(n0 + row) * K + k0 + k4 * 4);
            }
        } else {
            #pragma unroll
            for (int i = 0; i < BITER; i++) {
                int idx = i * THREADS + tid;
                int row = idx / (BN / 4), n4 = idx % (BN / 4);
                cpasync16(bb + (row * LB + n4 * 4) * 4,
                          B + (long)(k0 + row) * N + n0 + n4 * 4);
            }
        }
        CP_COMMIT();
    };
    auto compute = [&](int buf) {
        const float* As = sm + buf * (ASZ + BSZE);
        const float* Bs = As + ASZ;
        #pragma unroll
        for (int k8 = 0; k8 < BK / 8; k8++) {
            uint32_t af[MI][4], bf[NI][2];
            #pragma unroll
            for (int mi = 0; mi < MI; mi++) {
                int mr = mW + mi * 16 + r;
                af[mi][0] = f2u(As[mr * LA + k8 * 8 + cq]);
                af[mi][1] = f2u(As[(mr + 8) * LA + k8 * 8 + cq]);
                af[mi][2] = f2u(As[mr * LA + k8 * 8 + cq + 4]);
                af[mi][3] = f2u(As[(mr + 8) * LA + k8 * 8 + cq + 4]);
            }
            #pragma unroll
            for (int ni = 0; ni < NI; ni++) {
                int nc = nW + ni * 8 + r;
                if constexpr (BT) {
                    bf[ni][0] = f2u(Bs[nc * LA + k8 * 8 + cq]);
                    bf[ni][1] = f2u(Bs[nc * LA + k8 * 8 + cq + 4]);
                } else {
                    bf[ni][0] = f2u(Bs[(k8 * 8 + cq) * LB + nc]);
                    bf[ni][1] = f2u(Bs[(k8 * 8 + cq + 4) * LB + nc]);
                }
            }
            #pragma unroll
            for (int mi = 0; mi < MI; mi++)
                #pragma unroll
                for (int ni = 0; ni < NI; ni++)
                    mma8(acc[mi][ni], af[mi], bf[ni]);
        }
    };

    const int NTILES = K / BK;
    #pragma unroll
    for (int s = 0; s < STAGES - 1; s++) issue(s * BK, s);

    for (int t = 0; t < NTILES; t++) {
        if (t + STAGES - 1 < NTILES) {
            issue((t + STAGES - 1) * BK, (t + STAGES - 1) % STAGES);
            CP_WAIT(STAGES - 1);
        } else {
            int rem = NTILES - 1 - t;
            if constexpr (STAGES >= 4) { if (rem == 2) CP_WAIT(2); }
            if (rem == 1) CP_WAIT(1);
            else if (rem == 0) CP_WAIT(0);
        }
        __syncthreads();
        compute(t % STAGES);
        __syncthreads();
    }

    #pragma unroll
    for (int mi = 0; mi < MI; mi++) {
        int row = m0 + mW + mi * 16 + r;
        #pragma unroll
        for (int ni = 0; ni < NI; ni++) {
            int col = n0 + nW + ni * 8 + 2 * cq;
            float2 v0 = make_float2(acc[mi][ni][0], acc[mi][ni][1]);
            float2 v1 = make_float2(acc[mi][ni][2], acc[mi][ni][3]);
            if constexpr (BIAS) {
                float b0 = bias[col], b1 = bias[col + 1];
                v0.x += b0; v0.y += b1; v1.x += b0; v1.y += b1;
            }
            if constexpr (HOUT) {
                __half* Ch = (__half*)C;
                *(__half2*)(Ch + (long)row * N + col)       = __floats2half2_rn(v0.x, v0.y);
                *(__half2*)(Ch + (long)(row + 8) * N + col) = __floats2half2_rn(v1.x, v1.y);
            } else {
                if constexpr (RNA) {
                    v0.x = tf32r(v0.x); v0.y = tf32r(v0.y);
                    v1.x = tf32r(v1.x); v1.y = tf32r(v1.y);
                }
                *(float2*)(C + (long)row * N + col) = v0;
                *(float2*)(C + (long)(row + 8) * N + col) = v1;
            }
        }
    }
}

// ---------------- fp16 GEMM for the final projection (cp.async) ----------------
#define HBM 128
#define HBN 128
#define HBK 64
#define HLA 72            // halves per row (BK + 8 pad)
#define HSTG ((HBM + HBN) * HLA)   // halves per stage = 18432 (36864 B)

__global__ void __launch_bounds__(128, 2) gemm_h(
    const __half* __restrict__ A, const __half* __restrict__ B,
    float* __restrict__ C, const float* __restrict__ bias,
    int M, int N, int K)
{
    extern __shared__ __half smh[];

    const int tid  = threadIdx.x;
    const int lane = tid & 31;
    const int warp = tid >> 5;
    const int r  = lane >> 2;
    const int cq = lane & 3;
    const int wm = warp >> 1, wn = warp & 1;
    const int mW = wm * 64, nW = wn * 64;
    const int m0 = blockIdx.y * HBM;
    const int n0 = blockIdx.x * HBN;

    float acc[4][8][4];
    #pragma unroll
    for (int mi = 0; mi < 4; mi++)
        #pragma unroll
        for (int ni = 0; ni < 8; ni++)
            #pragma unroll
            for (int j = 0; j < 4; j++) acc[mi][ni][j] = 0.0f;

    auto issue = [&](int k0, int buf) {
        __half* As = smh + buf * HSTG;
        __half* Bs = As + HBM * HLA;
        uint32_t ab = smem_u32(As);
        uint32_t bb = smem_u32(Bs);
        #pragma unroll
        for (int i = 0; i < 8; i++) {
            int idx = i * 128 + tid;
            int row = idx >> 3, c8 = idx & 7;
            cpasync16(ab + (row * HLA + c8 * 8) * 2,
                      A + (long)(m0 + row) * K + k0 + c8 * 8);
        }
        #pragma unroll
        for (int i = 0; i < 8; i++) {
            int idx = i * 128 + tid;
            int row = idx >> 3, c8 = idx & 7;
            cpasync16(bb + (row * HLA + c8 * 8) * 2,
                      B + (long)(n0 + row) * K + k0 + c8 * 8);
        }
        CP_COMMIT();
    };
    auto compute = [&](int buf) {
        const __half* As = smh + buf * HSTG;
        const __half* Bs = As + HBM * HLA;
        #pragma unroll
        for (int k16 = 0; k16 < 4; k16++) {
            uint32_t af[4][4], bf[8][2];
            #pragma unroll
            for (int mi = 0; mi < 4; mi++) {
                int mr = mW + mi * 16 + r;
                const __half* p0 = As + mr * HLA + k16 * 16 + 2 * cq;
                const __half* p1 = As + (mr + 8) * HLA + k16 * 16 + 2 * cq;
                af[mi][0] = *(const uint32_t*)p0;
                af[mi][1] = *(const uint32_t*)p1;
                af[mi][2] = *(const uint32_t*)(p0 + 8);
                af[mi][3] = *(const uint32_t*)(p1 + 8);
            }
            #pragma unroll
            for (int ni = 0; ni < 8; ni++) {
                int nc = nW + ni * 8 + r;
                const __half* p = Bs + nc * HLA + k16 * 16 + 2 * cq;
                bf[ni][0] = *(const uint32_t*)p;
                bf[ni][1] = *(const uint32_t*)(p + 8);
            }
            #pragma unroll
            for (int mi = 0; mi < 4; mi++)
                #pragma unroll
                for (int ni = 0; ni < 8; ni++)
                    mma16h(acc[mi][ni], af[mi], bf[ni]);
        }
    };

    const int NTILES = K / HBK;   // 16
    issue(0, 0);
    for (int t = 0; t < NTILES; t++) {
        if (t + 1 < NTILES) { issue((t + 1) * HBK, (t + 1) & 1); CP_WAIT(1); }
        else CP_WAIT(0);
        __syncthreads();
        compute(t & 1);
        __syncthreads();
    }

    #pragma unroll
    for (int mi = 0; mi < 4; mi++) {
        int row = m0 + mW + mi * 16 + r;
        #pragma unroll
        for (int ni = 0; ni < 8; ni++) {
            int col = n0 + nW + ni * 8 + 2 * cq;
            float b0 = bias[col], b1 = bias[col + 1];
            *(float2*)(C + (long)row * N + col) =
                make_float2(acc[mi][ni][0] + b0, acc[mi][ni][1] + b1);
            *(float2*)(C + (long)(row + 8) * N + col) =
                make_float2(acc[mi][ni][2] + b0, acc[mi][ni][3] + b1);
        }
    }
}

// ---------------- b2[e] = dot(Wo[e,:], bv) + bo[e]  (exact fp32) ----------------
__global__ void __launch_bounds__(256) k_b2(const float* __restrict__ Wo,
                                            const float* __restrict__ bv,
                                            const float* __restrict__ bo) {
    int e = blockIdx.x * 256 + threadIdx.x;
    const float4* wo = (const float4*)(Wo + (long)e * HIDDEN);
    const float4* bvv = (const float4*)bv;
    float acc = 0.0f;
    #pragma unroll 4
    for (int i = 0; i < HIDDEN / 4; i++) {
        float4 a = wo[i], b = bvv[i];
        acc = fmaf(a.x, b.x, acc); acc = fmaf(a.y, b.y, acc);
        acc = fmaf(a.z, b.z, acc); acc = fmaf(a.w, b.w, acc);
    }
    g_b2[e] = acc + bo[e];
}

// ---------------- fused attention: persistent, fp16 mma, ldmatrix.trans Y ----------------
#define LQ2 1032          // floats per X row in fp32 staging
#define LQH 1048          // halves per X row in fp16 view
#define OFF_X  0
#define OFF_SP (3 * TT * LQ2)
#define OFF_P  (OFF_SP + 16 * 16 * TT)
#define OFF_M  (OFF_P + 16 * 24)
#define OFF_L  (OFF_M + 16)
#define OFF_SC (OFF_L + 16)
#define OFF_LG (OFF_SC + 16)
#define FUSED_SMEM ((OFF_LG + SEGLEN) * 4)
#define FGRID 148

__global__ void __launch_bounds__(512, 1) fused_attn(
    const float* __restrict__ X, const float* __restrict__ logits,
    __half* __restrict__ Y)
{
    extern __shared__ float sm[];
    float*  Xs  = sm + OFF_X;
    float*  Sp  = sm + OFF_SP;
    __half* Psh = (__half*)(sm + OFF_P);      // [16][24] halves
    float*  mS  = sm + OFF_M;
    float*  lS  = sm + OFF_L;
    float*  scS = sm + OFF_SC;
    float*  lgS = sm + OFF_LG;

    const int tid  = threadIdx.x;
    const int lane = tid & 31;
    const int w    = tid >> 5;        // 0..15, d-chunk = [w*64, w*64+64)
    const int r    = lane >> 2;
    const int cq   = lane & 3;

    const int nb = (BSZ - blockIdx.x + FGRID - 1) / FGRID;   // 4 or 3
    const int NG = nb * (SEGLEN / TT);

    auto issueG = [&](int g) {
        int bcur = blockIdx.x + (g >> 4) * FGRID;
        int it   = g & 15;
        const float* src0 = X + (long)bcur * SEGLEN * HIDDEN + (long)it * TT * HIDDEN;
        uint32_t dstb = smem_u32(Xs + (g % 3) * TT * LQ2);
        #pragma unroll
        for (int i = 0; i < 8; i++) {
            int idx = i * 512 + tid;          // 4096 float4 per stage
            int row = idx >> 8, c4 = idx & 255;
            cpasync16(dstb + (row * LQ2 + c4 * 4) * 4, src0 + row * HIDDEN + c4 * 4);
        }
        CP_COMMIT();
    };
    issueG(0); issueG(1);

    // Q2 fp16 fragments in registers
    uint32_t afq[4][4];
    #pragma unroll
    for (int k16 = 0; k16 < 4; k16++) {
        int col = w * 64 + k16 * 16 + 2 * cq;
        const __half* q0 = g_q2h + (long)r * HIDDEN + col;
        const __half* q1 = g_q2h + (long)(r + 8) * HIDDEN + col;
        afq[k16][0] = *(const uint32_t*)q0;
        afq[k16][1] = *(const uint32_t*)q1;
        afq[k16][2] = *(const uint32_t*)(q0 + 8);
        afq[k16][3] = *(const uint32_t*)(q1 + 8);
    }

    float acc[8][4];
    #pragma unroll
    for (int ni = 0; ni < 8; ni++)
        #pragma unroll
        for (int j = 0; j < 4; j++) acc[ni][j] = 0.0f;

    __syncthreads();

    for (int g = 0; g < NG; g++) {
        const int it   = g & 15;
        const int bcur = blockIdx.x + (g >> 4) * FGRID;

        if (g + 2 < NG) { issueG(g + 2); CP_WAIT(2); }
        else if (NG - 1 - g == 1) CP_WAIT(1);
        else CP_WAIT(0);

        float*  XtF = Xs + (g % 3) * TT * LQ2;
        __half* hb  = (__half*)XtF;

        // ---- in-place fp32 -> fp16 convert (each thread reads exactly what it copied) ----
        float4 xv[8];
        #pragma unroll
        for (int i = 0; i < 8; i++) {
            int idx = i * 512 + tid;
            int row = idx >> 8, c4 = idx & 255;
            xv[i] = *(const float4*)(XtF + row * LQ2 + c4 * 4);
        }
        __syncthreads();   // all reads done before overwrite
        #pragma unroll
        for (int i = 0; i < 8; i++) {
            int idx = i * 512 + tid;
            int row = idx >> 8, c4 = idx & 255;
            __half2* dst = (__half2*)(hb + row * LQH + c4 * 4);
            dst[0] = __floats2half2_rn(xv[i].x, xv[i].y);
            dst[1] = __floats2half2_rn(xv[i].z, xv[i].w);
        }
        if (it == 0) {
            if (tid < 256) lgS[tid] = logits[(long)bcur * SEGLEN + tid];
            if (tid < 16) { mS[tid] = -INFINITY; lS[tid] = 0.0f; }
        }
        __syncthreads();   // halves + state visible

        // ---- scores (fp16): warp covers d in [w*64, w*64+64) ----
        {
            float sacc[2][4] = {{0,0,0,0},{0,0,0,0}};
            #pragma unroll
            for (int k16 = 0; k16 < 4; k16++) {
                int kk = w * 64 + k16 * 16;
                uint32_t bf[2][2];
                #pragma unroll
                for (int nt = 0; nt < 2; nt++) {
                    int nc = nt * 8 + r;
                    const __half* p = hb + nc * LQH + kk + 2 * cq;
                    bf[nt][0] = *(const uint32_t*)p;
                    bf[nt][1] = *(const uint32_t*)(p + 8);
                }
                mma16h(sacc[0], afq[k16], bf[0]);
                mma16h(sacc[1], afq[k16], bf[1]);
            }
            #pragma unroll
            for (int nt = 0; nt < 2; nt++) {
                int c0 = nt * 8 + 2 * cq;
                Sp[(w * 16 + r) * TT + c0]         = sacc[nt][0];
                Sp[(w * 16 + r) * TT + c0 + 1]     = sacc[nt][1];
                Sp[(w * 16 + r + 8) * TT + c0]     = sacc[nt][2];
                Sp[(w * 16 + r + 8) * TT + c0 + 1] = sacc[nt][3];
            }
        }
        __syncthreads();

        // ---- online softmax: thread (s = tid>>4, t = tid&15), tid < 256 ----
        if (tid < 256) {
            int s = tid >> 4, t = tid & 15;
            float accs = 0.0f;
            #pragma unroll
            for (int ww = 0; ww < 16; ww++) accs += Sp[(ww * 16 + s) * TT + t];
            float v = accs * SCALE + lgS[it * TT + t];
            float m_t = v;
            #pragma unroll
            for (int o = 8; o; o >>= 1) m_t = fmaxf(m_t, __shfl_xor_sync(0xffffffffu, m_t, o));
            float m_old = mS[s];
            float newm = fmaxf(m_old, m_t);
            float p = expf(v - newm);
            Psh[s * 24 + t] = __float2half_rn(p);
            float sum = p;
            #pragma unroll
            for (int o = 8; o; o >>= 1) sum += __shfl_xor_sync(0xffffffffu, sum, o);
            if (t == 0) {
                float scale = expf(m_old - newm); // 0 on first tile of segment
                lS[s] = lS[s] * scale + sum;
                mS[s] = newm;
                scS[s] = scale;
            }
        }
        __syncthreads();

        // ---- rescale Y acc, then Y += P @ X_tile (ldmatrix.trans B fragments) ----
        {
            float sc0 = scS[r], sc1 = scS[r + 8];
            #pragma unroll
            for (int ni = 0; ni < 8; ni++) {
                acc[ni][0] *= sc0; acc[ni][1] *= sc0;
                acc[ni][2] *= sc1; acc[ni][3] *= sc1;
            }
            uint32_t af[4];
            af[0] = *(const uint32_t*)(Psh + r * 24 + 2 * cq);
            af[1] = *(const uint32_t*)(Psh + (r + 8) * 24 + 2 * cq);
            af[2] = *(const uint32_t*)(Psh + r * 24 + 2 * cq + 8);
            af[3] = *(const uint32_t*)(Psh + (r + 8) * 24 + 2 * cq + 8);
            #pragma unroll
            for (int j = 0; j < 4; j++) {
                int t  = lane & 15;
                int cb = w * 64 + j * 16 + ((lane >> 4) << 3);
                uint32_t b0, b1, b2, b3;
                ldsm4t(b0, b1, b2, b3, smem_u32(hb + t * LQH + cb));
                uint32_t bfA[2] = { b0, b1 };
                uint32_t bfB[2] = { b2, b3 };
                mma16h(acc[2 * j],     af, bfA);
                mma16h(acc[2 * j + 1], af, bfB);
            }
        }

        // ---- segment end: write Y as fp16 (RNE) ----
        if (it == 15) {
            float inv0 = 1.0f / lS[r];
            float inv1 = 1.0f / lS[r + 8];
            __half* Y0 = Y + ((long)bcur * SLOTS + r) * HIDDEN;
            __half* Y1 = Y + ((long)bcur * SLOTS + r + 8) * HIDDEN;
            #pragma unroll
            for (int ni = 0; ni < 8; ni++) {
                int col = w * 64 + ni * 8 + 2 * cq;
                *(__half2*)(Y0 + col) = __floats2half2_rn(acc[ni][0] * inv0, acc[ni][1] * inv0);
                *(__half2*)(Y1 + col) = __floats2half2_rn(acc[ni][2] * inv1, acc[ni][3] * inv1);
            }
        }
        __syncthreads();   // stage halves + Psh/scS/mS/lS protected before next tile
    }
}

// ---------------- launch: fork W2 branch onto a second stream ----------------
extern "C" void kernel_launch(void* const* d_in, const int* in_sizes, int n_in,
                              void* d_out, int out_size) {
    const float* X      = (const float*)d_in[0];   // [512,256,1024]
    const float* logits = (const float*)d_in[1];   // [512,256]
    const float* LQ     = (const float*)d_in[2];   // [16,1024]
    const float* Wq     = (const float*)d_in[3];
    const float* bq     = (const float*)d_in[4];
    const float* Wk     = (const float*)d_in[5];
    // d_in[6] = bk: cancels in softmax, unused
    const float* Wv     = (const float*)d_in[7];
    const float* bv     = (const float*)d_in[8];
    const float* Wo     = (const float*)d_in[9];
    const float* bo     = (const float*)d_in[10];
    float* out = (float*)d_out;

    float *wop, *wvp, *q1p, *b2p;
    __half *q2hp, *w2hp, *yhp;
    cudaGetSymbolAddress((void**)&wop,  g_wo);
    cudaGetSymbolAddress((void**)&wvp,  g_wv);
    cudaGetSymbolAddress((void**)&q1p,  g_q1);
    cudaGetSymbolAddress((void**)&q2hp, g_q2h);
    cudaGetSymbolAddress((void**)&w2hp, g_w2h);
    cudaGetSymbolAddress((void**)&b2p,  g_b2);
    cudaGetSymbolAddress((void**)&yhp,  g_yh);

    // smem opt-in (idempotent)
    const int QSM = (SLOTS * HIDDEN + 16 * 16 * 16) * 4;   // 81920
    cudaFuncSetAttribute((const void*)k_q1,
                         cudaFuncAttributeMaxDynamicSharedMemorySize, QSM);
    cudaFuncSetAttribute((const void*)k_q2,
                         cudaFuncAttributeMaxDynamicSharedMemorySize, QSM);
    cudaFuncSetAttribute((const void*)gemm_cpa<64,64,32,2,2,3,false,false,false,true,1>,
                         cudaFuncAttributeMaxDynamicSharedMemorySize, 58368);
    cudaFuncSetAttribute((const void*)gemm_h,
                         cudaFuncAttributeMaxDynamicSharedMemorySize, 2 * HSTG * 2);
    cudaFuncSetAttribute((const void*)fused_attn,
                         cudaFuncAttributeMaxDynamicSharedMemorySize, FUSED_SMEM);

    // fork/join infrastructure (per-call; graph replays never re-enter here)
    cudaStream_t s2;
    cudaStreamCreateWithFlags(&s2, cudaStreamNonBlocking);
    cudaEvent_t e1, e2;
    cudaEventCreateWithFlags(&e1, cudaEventDisableTiming);
    cudaEventCreateWithFlags(&e2, cudaEventDisableTiming);

    cudaEventRecord(e1, 0);
    cudaStreamWaitEvent(s2, e1, 0);

    // ---- side branch (stream s2): W2 path, joins before gemm_h ----
    k_round2<<<dim3(1024, 2), 256, 0, s2>>>(wop, Wo, wvp, Wv);
    k_b2<<<4, 256, 0, s2>>>(Wo, bv, bo);
    gemm_cpa<64, 64, 32, 2, 2, 3, false, false, false, true, 1><<<dim3(16, 16), 128, 58368, s2>>>(
        wop, wvp, (float*)w2hp, nullptr, 1024, 1024, 1024);
    cudaEventRecord(e2, s2);

    // ---- main branch: exact fp32 q-chain -> fused attention ----
    k_q1<<<64, 256, QSM>>>(LQ, Wq, bq, q1p);
    k_q2<<<64, 256, QSM>>>(q1p, Wk, q2hp);
    fused_attn<<<FGRID, 512, FUSED_SMEM>>>(X, logits, yhp);

    // ---- join, then final projection ----
    cudaStreamWaitEvent((cudaStream_t)0, e2, 0);
    gemm_h<<<dim3(8, 64), 128, 2 * HSTG * 2>>>(
        yhp, w2hp, out, b2p, BSZ * SLOTS, HIDDEN, HIDDEN);
}

// round 15
// speedup vs baseline: 1.0608x; 1.0608x over previous
#include <cuda_runtime.h>
#include <cuda_fp16.h>
#include <cstdint>

#define HIDDEN 1024
#define SLOTS 16
#define BSZ 512
#define SEGLEN 256
#define TT 16            // t-tile in fused attention
#define SCALE 0.03125f   // 1/sqrt(1024)

// ---------------- scratch (device globals; no allocation) ----------------
__device__ float  g_wo[HIDDEN * HIDDEN];                  // RNA-rounded Wo
__device__ float  g_wv[HIDDEN * HIDDEN];                  // RNA-rounded Wv
__device__ float  g_q1[SLOTS * HIDDEN];                   // tf32-exact q1
__device__ __half g_q2h[SLOTS * HIDDEN];                  // fp16 Q2
__device__ __half g_w2h[HIDDEN * HIDDEN];                 // fp16 W2 = Wo@Wv
__device__ float  g_b2[HIDDEN];
__device__ __half g_yh[(size_t)BSZ * SLOTS * HIDDEN];     // fp16 Y [b][s][d]

// ---------------- helpers ----------------
__device__ __forceinline__ float tf32r(float x) {
    uint32_t u;
    asm("cvt.rna.tf32.f32 %0, %1;" : "=r"(u) : "f"(x));
    return __uint_as_float(u);
}
__device__ __forceinline__ float4 tf32r4(float4 v) {
    return make_float4(tf32r(v.x), tf32r(v.y), tf32r(v.z), tf32r(v.w));
}
__device__ __forceinline__ uint32_t f2u(float x) { return __float_as_uint(x); }

__device__ __forceinline__ void mma8(float* c, const uint32_t* a, const uint32_t* b) {
    asm volatile(
        "mma.sync.aligned.m16n8k8.row.col.f32.tf32.tf32.f32 "
        "{%0,%1,%2,%3},{%4,%5,%6,%7},{%8,%9},{%0,%1,%2,%3};"
        : "+f"(c[0]), "+f"(c[1]), "+f"(c[2]), "+f"(c[3])
        : "r"(a[0]), "r"(a[1]), "r"(a[2]), "r"(a[3]), "r"(b[0]), "r"(b[1]));
}
__device__ __forceinline__ void mma16h(float* c, const uint32_t* a, const uint32_t* b) {
    asm volatile(
        "mma.sync.aligned.m16n8k16.row.col.f32.f16.f16.f32 "
        "{%0,%1,%2,%3},{%4,%5,%6,%7},{%8,%9},{%0,%1,%2,%3};"
        : "+f"(c[0]), "+f"(c[1]), "+f"(c[2]), "+f"(c[3])
        : "r"(a[0]), "r"(a[1]), "r"(a[2]), "r"(a[3]), "r"(b[0]), "r"(b[1]));
}
__device__ __forceinline__ void ldsm4t(uint32_t& r0, uint32_t& r1, uint32_t& r2, uint32_t& r3,
                                       uint32_t a) {
    asm volatile("ldmatrix.sync.aligned.m8n8.x4.trans.shared.b16 {%0,%1,%2,%3}, [%4];"
                 : "=r"(r0), "=r"(r1), "=r"(r2), "=r"(r3) : "r"(a));
}

__device__ __forceinline__ uint32_t smem_u32(const void* p) {
    uint32_t a;
    asm("{ .reg .u64 t; cvta.to.shared.u64 t, %1; cvt.u32.u64 %0, t; }" : "=r"(a) : "l"(p));
    return a;
}
__device__ __forceinline__ void cpasync16(uint32_t dst, const void* src) {
    asm volatile("cp.async.cg.shared.global [%0], [%1], 16;" :: "r"(dst), "l"(src));
}
#define CP_COMMIT() asm volatile("cp.async.commit_group;")
#define CP_WAIT(n)  asm volatile("cp.async.wait_group %0;" :: "n"(n))

// ---------------- batched RNA round-copy (side branch only) ----------------
__global__ void __launch_bounds__(256) k_round2(
    float* d0, const float* s0, float* d1, const float* s1) {
    const float* s = blockIdx.y ? s1 : s0;
    float* d = blockIdx.y ? d1 : d0;
    int i = blockIdx.x * 256 + threadIdx.x;
    ((float4*)d)[i] = tf32r4(((const float4*)s)[i]);
}

// ---------------- multi-stage cp.async tf32 GEMM ----------------
// C[m,n] = sum_k A[m,k] * (BT ? B[n,k] : B[k,n])  (+ bias[n] if BIAS)
// CVT: in-place RNA tf32 convert of the stage before compute (for raw fp32 inputs).
// Without CVT, inputs must already be tf32-exact.
template <int BM, int BN, int BK, int WM, int WN, int STAGES,
          bool BT, bool BIAS, bool RNA, bool HOUT, bool CVT, int MINCTA>
__global__ void __launch_bounds__(WM * WN * 32, MINCTA) gemm_cpa(
    const float* __restrict__ A, const float* __restrict__ B,
    float* __restrict__ C, const float* __restrict__ bias,
    int M, int N, int K)
{
    constexpr int THREADS = WM * WN * 32;
    constexpr int LA = BK + 8;
    constexpr int LB = BN + 8;
    constexpr int ASZ = BM * LA;
    constexpr int BSZE = BT ? BN * LA : BK * LB;
    constexpr int AITER = BM * BK / 4 / THREADS;
    constexpr int BITER = BN * BK / 4 / THREADS;

    extern __shared__ float sm[];

    const int tid  = threadIdx.x;
    const int lane = tid & 31;
    const int warp = tid >> 5;
    const int r  = lane >> 2;
    const int cq = lane & 3;
    const int wm = warp / WN, wn = warp % WN;
    constexpr int WTM = BM / WM, WTN = BN / WN;
    constexpr int MI = WTM / 16, NI = WTN / 8;
    const int mW = wm * WTM, nW = wn * WTN;
    const int m0 = blockIdx.y * BM;
    const int n0 = blockIdx.x * BN;

    float acc[MI][NI][4];
    #pragma unroll
    for (int mi = 0; mi < MI; mi++)
        #pragma unroll
        for (int ni = 0; ni < NI; ni++)
            #pragma unroll
            for (int j = 0; j < 4; j++) acc[mi][ni][j] = 0.0f;

    auto issue = [&](int k0, int buf) {
        float* As = sm + buf * (ASZ + BSZE);
        float* Bs = As + ASZ;
        uint32_t ab = smem_u32(As);
        uint32_t bb = smem_u32(Bs);
        #pragma unroll
        for (int i = 0; i < AITER; i++) {
            int idx = i * THREADS + tid;
            int row = idx / (BK / 4), k4 = idx % (BK / 4);
            cpasync16(ab + (row * LA + k4 * 4) * 4,
                      A + (long)(m0 + row) * K + k0 + k4 * 4);
        }
        if constexpr (BT) {
            #pragma unroll
            for (int i = 0; i < BITER; i++) {
                int idx = i * THREADS + tid;
                int row = idx / (BK / 4), k4 = idx % (BK / 4);
                cpasync16(bb + (row * LA + k4 * 4) * 4,
                          B + (long)(n0 + row) * K + k0 + k4 * 4);
            }
        } else {
            #pragma unroll
            for (int i = 0; i < BITER; i++) {
                int idx = i * THREADS + tid;
                int row = idx / (BN / 4), n4 = idx % (BN / 4);
                cpasync16(bb + (row * LB + n4 * 4) * 4,
                          B + (long)(k0 + row) * N + n0 + n4 * 4);
            }
        }
        CP_COMMIT();
    };
    auto compute = [&](int buf) {
        const float* As = sm + buf * (ASZ + BSZE);
        const float* Bs = As + ASZ;
        #pragma unroll
        for (int k8 = 0; k8 < BK / 8; k8++) {
            uint32_t af[MI][4], bf[NI][2];
            #pragma unroll
            for (int mi = 0; mi < MI; mi++) {
                int mr = mW + mi * 16 + r;
                af[mi][0] = f2u(As[mr * LA + k8 * 8 + cq]);
                af[mi][1] = f2u(As[(mr + 8) * LA + k8 * 8 + cq]);
                af[mi][2] = f2u(As[mr * LA + k8 * 8 + cq + 4]);
                af[mi][3] = f2u(As[(mr + 8) * LA + k8 * 8 + cq + 4]);
            }
            #pragma unroll
            for (int ni = 0; ni < NI; ni++) {
                int nc = nW + ni * 8 + r;
                if constexpr (BT) {
                    bf[ni][0] = f2u(Bs[nc * LA + k8 * 8 + cq]);
                    bf[ni][1] = f2u(Bs[nc * LA + k8 * 8 + cq + 4]);
                } else {
                    bf[ni][0] = f2u(Bs[(k8 * 8 + cq) * LB + nc]);
                    bf[ni][1] = f2u(Bs[(k8 * 8 + cq + 4) * LB + nc]);
                }
            }
            #pragma unroll
            for (int mi = 0; mi < MI; mi++)
                #pragma unroll
                for (int ni = 0; ni < NI; ni++)
                    mma8(acc[mi][ni], af[mi], bf[ni]);
        }
    };

    const int NTILES = K / BK;
    #pragma unroll
    for (int s = 0; s < STAGES - 1; s++) issue(s * BK, s);

    for (int t = 0; t < NTILES; t++) {
        if (t + STAGES - 1 < NTILES) {
            issue((t + STAGES - 1) * BK, (t + STAGES - 1) % STAGES);
            CP_WAIT(STAGES - 1);
        } else {
            int rem = NTILES - 1 - t;
            if constexpr (STAGES >= 4) { if (rem == 2) CP_WAIT(2); }
            if (rem == 1) CP_WAIT(1);
            else if (rem == 0) CP_WAIT(0);
        }
        __syncthreads();
        if constexpr (CVT) {
            // unbiased in-place RNA tf32 conversion (padding junk harmless)
            float* base = sm + (t % STAGES) * (ASZ + BSZE);
            constexpr int TOT4 = (ASZ + BSZE) / 4;
            for (int i = tid; i < TOT4; i += THREADS) {
                float4* p = (float4*)base + i;
                *p = tf32r4(*p);
            }
            __syncthreads();
        }
        compute(t % STAGES);
        __syncthreads();
    }

    #pragma unroll
    for (int mi = 0; mi < MI; mi++) {
        int row = m0 + mW + mi * 16 + r;
        #pragma unroll
        for (int ni = 0; ni < NI; ni++) {
            int col = n0 + nW + ni * 8 + 2 * cq;
            float2 v0 = make_float2(acc[mi][ni][0], acc[mi][ni][1]);
            float2 v1 = make_float2(acc[mi][ni][2], acc[mi][ni][3]);
            if constexpr (BIAS) {
                float b0 = bias[col], b1 = bias[col + 1];
                v0.x += b0; v0.y += b1; v1.x += b0; v1.y += b1;
            }
            if constexpr (HOUT) {
                __half* Ch = (__half*)C;
                *(__half2*)(Ch + (long)row * N + col)       = __floats2half2_rn(v0.x, v0.y);
                *(__half2*)(Ch + (long)(row + 8) * N + col) = __floats2half2_rn(v1.x, v1.y);
            } else {
                if constexpr (RNA) {
                    v0.x = tf32r(v0.x); v0.y = tf32r(v0.y);
                    v1.x = tf32r(v1.x); v1.y = tf32r(v1.y);
                }
                *(float2*)(C + (long)row * N + col) = v0;
                *(float2*)(C + (long)(row + 8) * N + col) = v1;
            }
        }
    }
}

// ---------------- fp16 GEMM for the final projection (cp.async) ----------------
#define HBM 128
#define HBN 128
#define HBK 64
#define HLA 72            // halves per row (BK + 8 pad)
#define HSTG ((HBM + HBN) * HLA)   // halves per stage = 18432 (36864 B)

__global__ void __launch_bounds__(128, 2) gemm_h(
    const __half* __restrict__ A, const __half* __restrict__ B,
    float* __restrict__ C, const float* __restrict__ bias,
    int M, int N, int K)
{
    extern __shared__ __half smh[];

    const int tid  = threadIdx.x;
    const int lane = tid & 31;
    const int warp = tid >> 5;
    const int r  = lane >> 2;
    const int cq = lane & 3;
    const int wm = warp >> 1, wn = warp & 1;
    const int mW = wm * 64, nW = wn * 64;
    const int m0 = blockIdx.y * HBM;
    const int n0 = blockIdx.x * HBN;

    float acc[4][8][4];
    #pragma unroll
    for (int mi = 0; mi < 4; mi++)
        #pragma unroll
        for (int ni = 0; ni < 8; ni++)
            #pragma unroll
            for (int j = 0; j < 4; j++) acc[mi][ni][j] = 0.0f;

    auto issue = [&](int k0, int buf) {
        __half* As = smh + buf * HSTG;
        __half* Bs = As + HBM * HLA;
        uint32_t ab = smem_u32(As);
        uint32_t bb = smem_u32(Bs);
        #pragma unroll
        for (int i = 0; i < 8; i++) {
            int idx = i * 128 + tid;
            int row = idx >> 3, c8 = idx & 7;
            cpasync16(ab + (row * HLA + c8 * 8) * 2,
                      A + (long)(m0 + row) * K + k0 + c8 * 8);
        }
        #pragma unroll
        for (int i = 0; i < 8; i++) {
            int idx = i * 128 + tid;
            int row = idx >> 3, c8 = idx & 7;
            cpasync16(bb + (row * HLA + c8 * 8) * 2,
                      B + (long)(n0 + row) * K + k0 + c8 * 8);
        }
        CP_COMMIT();
    };
    auto compute = [&](int buf) {
        const __half* As = smh + buf * HSTG;
        const __half* Bs = As + HBM * HLA;
        #pragma unroll
        for (int k16 = 0; k16 < 4; k16++) {
            uint32_t af[4][4], bf[8][2];
            #pragma unroll
            for (int mi = 0; mi < 4; mi++) {
                int mr = mW + mi * 16 + r;
                const __half* p0 = As + mr * HLA + k16 * 16 + 2 * cq;
                const __half* p1 = As + (mr + 8) * HLA + k16 * 16 + 2 * cq;
                af[mi][0] = *(const uint32_t*)p0;
                af[mi][1] = *(const uint32_t*)p1;
                af[mi][2] = *(const uint32_t*)(p0 + 8);
                af[mi][3] = *(const uint32_t*)(p1 + 8);
            }
            #pragma unroll
            for (int ni = 0; ni < 8; ni++) {
                int nc = nW + ni * 8 + r;
                const __half* p = Bs + nc * HLA + k16 * 16 + 2 * cq;
                bf[ni][0] = *(const uint32_t*)p;
                bf[ni][1] = *(const uint32_t*)(p + 8);
            }
            #pragma unroll
            for (int mi = 0; mi < 4; mi++)
                #pragma unroll
                for (int ni = 0; ni < 8; ni++)
                    mma16h(acc[mi][ni], af[mi], bf[ni]);
        }
    };

    const int NTILES = K / HBK;   // 16
    issue(0, 0);
    for (int t = 0; t < NTILES; t++) {
        if (t + 1 < NTILES) { issue((t + 1) * HBK, (t + 1) & 1); CP_WAIT(1); }
        else CP_WAIT(0);
        __syncthreads();
        compute(t & 1);
        __syncthreads();
    }

    #pragma unroll
    for (int mi = 0; mi < 4; mi++) {
        int row = m0 + mW + mi * 16 + r;
        #pragma unroll
        for (int ni = 0; ni < 8; ni++) {
            int col = n0 + nW + ni * 8 + 2 * cq;
            float b0 = bias[col], b1 = bias[col + 1];
            *(float2*)(C + (long)row * N + col) =
                make_float2(acc[mi][ni][0] + b0, acc[mi][ni][1] + b1);
            *(float2*)(C + (long)(row + 8) * N + col) =
                make_float2(acc[mi][ni][2] + b0, acc[mi][ni][3] + b1);
        }
    }
}

// ---------------- b2[e] = dot(Wo[e,:], bv) + bo[e]  (exact fp32) ----------------
__global__ void __launch_bounds__(256) k_b2(const float* __restrict__ Wo,
                                            const float* __restrict__ bv,
                                            const float* __restrict__ bo) {
    int e = blockIdx.x * 256 + threadIdx.x;
    const float4* wo = (const float4*)(Wo + (long)e * HIDDEN);
    const float4* bvv = (const float4*)bv;
    float acc = 0.0f;
    #pragma unroll 4
    for (int i = 0; i < HIDDEN / 4; i++) {
        float4 a = wo[i], b = bvv[i];
        acc = fmaf(a.x, b.x, acc); acc = fmaf(a.y, b.y, acc);
        acc = fmaf(a.z, b.z, acc); acc = fmaf(a.w, b.w, acc);
    }
    g_b2[e] = acc + bo[e];
}

// ---------------- fused attention: persistent, fp16 mma, ldmatrix.trans Y ----------------
#define LQ2 1032          // floats per X row in fp32 staging
#define LQH 1048          // halves per X row in fp16 view
#define OFF_X  0
#define OFF_SP (3 * TT * LQ2)
#define OFF_P  (OFF_SP + 16 * 16 * TT)
#define OFF_M  (OFF_P + 16 * 24)
#define OFF_L  (OFF_M + 16)
#define OFF_SC (OFF_L + 16)
#define OFF_LG (OFF_SC + 16)
#define FUSED_SMEM ((OFF_LG + SEGLEN) * 4)
#define FGRID 148

__global__ void __launch_bounds__(512, 1) fused_attn(
    const float* __restrict__ X, const float* __restrict__ logits,
    __half* __restrict__ Y)
{
    extern __shared__ float sm[];
    float*  Xs  = sm + OFF_X;
    float*  Sp  = sm + OFF_SP;
    __half* Psh = (__half*)(sm + OFF_P);      // [16][24] halves
    float*  mS  = sm + OFF_M;
    float*  lS  = sm + OFF_L;
    float*  scS = sm + OFF_SC;
    float*  lgS = sm + OFF_LG;

    const int tid  = threadIdx.x;
    const int lane = tid & 31;
    const int w    = tid >> 5;        // 0..15, d-chunk = [w*64, w*64+64)
    const int r    = lane >> 2;
    const int cq   = lane & 3;

    const int nb = (BSZ - blockIdx.x + FGRID - 1) / FGRID;   // 4 or 3
    const int NG = nb * (SEGLEN / TT);

    auto issueG = [&](int g) {
        int bcur = blockIdx.x + (g >> 4) * FGRID;
        int it   = g & 15;
        const float* src0 = X + (long)bcur * SEGLEN * HIDDEN + (long)it * TT * HIDDEN;
        uint32_t dstb = smem_u32(Xs + (g % 3) * TT * LQ2);
        #pragma unroll
        for (int i = 0; i < 8; i++) {
            int idx = i * 512 + tid;          // 4096 float4 per stage
            int row = idx >> 8, c4 = idx & 255;
            cpasync16(dstb + (row * LQ2 + c4 * 4) * 4, src0 + row * HIDDEN + c4 * 4);
        }
        CP_COMMIT();
    };
    issueG(0); issueG(1);

    // Q2 fp16 fragments in registers
    uint32_t afq[4][4];
    #pragma unroll
    for (int k16 = 0; k16 < 4; k16++) {
        int col = w * 64 + k16 * 16 + 2 * cq;
        const __half* q0 = g_q2h + (long)r * HIDDEN + col;
        const __half* q1 = g_q2h + (long)(r + 8) * HIDDEN + col;
        afq[k16][0] = *(const uint32_t*)q0;
        afq[k16][1] = *(const uint32_t*)q1;
        afq[k16][2] = *(const uint32_t*)(q0 + 8);
        afq[k16][3] = *(const uint32_t*)(q1 + 8);
    }

    float acc[8][4];
    #pragma unroll
    for (int ni = 0; ni < 8; ni++)
        #pragma unroll
        for (int j = 0; j < 4; j++) acc[ni][j] = 0.0f;

    __syncthreads();

    for (int g = 0; g < NG; g++) {
        const int it   = g & 15;
        const int bcur = blockIdx.x + (g >> 4) * FGRID;

        if (g + 2 < NG) { issueG(g + 2); CP_WAIT(2); }
        else if (NG - 1 - g == 1) CP_WAIT(1);
        else CP_WAIT(0);

        float*  XtF = Xs + (g % 3) * TT * LQ2;
        __half* hb  = (__half*)XtF;

        // ---- in-place fp32 -> fp16 convert (each thread reads exactly what it copied) ----
        float4 xv[8];
        #pragma unroll
        for (int i = 0; i < 8; i++) {
            int idx = i * 512 + tid;
            int row = idx >> 8, c4 = idx & 255;
            xv[i] = *(const float4*)(XtF + row * LQ2 + c4 * 4);
        }
        __syncthreads();   // all reads done before overwrite
        #pragma unroll
        for (int i = 0; i < 8; i++) {
            int idx = i * 512 + tid;
            int row = idx >> 8, c4 = idx & 255;
            __half2* dst = (__half2*)(hb + row * LQH + c4 * 4);
            dst[0] = __floats2half2_rn(xv[i].x, xv[i].y);
            dst[1] = __floats2half2_rn(xv[i].z, xv[i].w);
        }
        if (it == 0) {
            if (tid < 256) lgS[tid] = logits[(long)bcur * SEGLEN + tid];
            if (tid < 16) { mS[tid] = -INFINITY; lS[tid] = 0.0f; }
        }
        __syncthreads();   // halves + state visible

        // ---- scores (fp16): warp covers d in [w*64, w*64+64) ----
        {
            float sacc[2][4] = {{0,0,0,0},{0,0,0,0}};
            #pragma unroll
            for (int k16 = 0; k16 < 4; k16++) {
                int kk = w * 64 + k16 * 16;
                uint32_t bf[2][2];
                #pragma unroll
                for (int nt = 0; nt < 2; nt++) {
                    int nc = nt * 8 + r;
                    const __half* p = hb + nc * LQH + kk + 2 * cq;
                    bf[nt][0] = *(const uint32_t*)p;
                    bf[nt][1] = *(const uint32_t*)(p + 8);
                }
                mma16h(sacc[0], afq[k16], bf[0]);
                mma16h(sacc[1], afq[k16], bf[1]);
            }
            #pragma unroll
            for (int nt = 0; nt < 2; nt++) {
                int c0 = nt * 8 + 2 * cq;
                Sp[(w * 16 + r) * TT + c0]         = sacc[nt][0];
                Sp[(w * 16 + r) * TT + c0 + 1]     = sacc[nt][1];
                Sp[(w * 16 + r + 8) * TT + c0]     = sacc[nt][2];
                Sp[(w * 16 + r + 8) * TT + c0 + 1] = sacc[nt][3];
            }
        }
        __syncthreads();

        // ---- online softmax: thread (s = tid>>4, t = tid&15), tid < 256 ----
        if (tid < 256) {
            int s = tid >> 4, t = tid & 15;
            float accs = 0.0f;
            #pragma unroll
            for (int ww = 0; ww < 16; ww++) accs += Sp[(ww * 16 + s) * TT + t];
            float v = accs * SCALE + lgS[it * TT + t];
            float m_t = v;
            #pragma unroll
            for (int o = 8; o; o >>= 1) m_t = fmaxf(m_t, __shfl_xor_sync(0xffffffffu, m_t, o));
            float m_old = mS[s];
            float newm = fmaxf(m_old, m_t);
            float p = expf(v - newm);
            Psh[s * 24 + t] = __float2half_rn(p);
            float sum = p;
            #pragma unroll
            for (int o = 8; o; o >>= 1) sum += __shfl_xor_sync(0xffffffffu, sum, o);
            if (t == 0) {
                float scale = expf(m_old - newm); // 0 on first tile of segment
                lS[s] = lS[s] * scale + sum;
                mS[s] = newm;
                scS[s] = scale;
            }
        }
        __syncthreads();

        // ---- rescale Y acc, then Y += P @ X_tile (ldmatrix.trans B fragments) ----
        {
            float sc0 = scS[r], sc1 = scS[r + 8];
            #pragma unroll
            for (int ni = 0; ni < 8; ni++) {
                acc[ni][0] *= sc0; acc[ni][1] *= sc0;
                acc[ni][2] *= sc1; acc[ni][3] *= sc1;
            }
            uint32_t af[4];
            af[0] = *(const uint32_t*)(Psh + r * 24 + 2 * cq);
            af[1] = *(const uint32_t*)(Psh + (r + 8) * 24 + 2 * cq);
            af[2] = *(const uint32_t*)(Psh + r * 24 + 2 * cq + 8);
            af[3] = *(const uint32_t*)(Psh + (r + 8) * 24 + 2 * cq + 8);
            #pragma unroll
            for (int j = 0; j < 4; j++) {
                int t  = lane & 15;
                int cb = w * 64 + j * 16 + ((lane >> 4) << 3);
                uint32_t b0, b1, b2, b3;
                ldsm4t(b0, b1, b2, b3, smem_u32(hb + t * LQH + cb));
                uint32_t bfA[2] = { b0, b1 };
                uint32_t bfB[2] = { b2, b3 };
                mma16h(acc[2 * j],     af, bfA);
                mma16h(acc[2 * j + 1], af, bfB);
            }
        }

        // ---- segment end: write Y as fp16 (RNE) ----
        if (it == 15) {
            float inv0 = 1.0f / lS[r];
            float inv1 = 1.0f / lS[r + 8];
            __half* Y0 = Y + ((long)bcur * SLOTS + r) * HIDDEN;
            __half* Y1 = Y + ((long)bcur * SLOTS + r + 8) * HIDDEN;
            #pragma unroll
            for (int ni = 0; ni < 8; ni++) {
                int col = w * 64 + ni * 8 + 2 * cq;
                *(__half2*)(Y0 + col) = __floats2half2_rn(acc[ni][0] * inv0, acc[ni][1] * inv0);
                *(__half2*)(Y1 + col) = __floats2half2_rn(acc[ni][2] * inv1, acc[ni][3] * inv1);
            }
        }
        __syncthreads();   // stage halves + Psh/scS/mS/lS protected before next tile
    }
}

// ---------------- launch: fork W2 branch onto a second stream ----------------
extern "C" void kernel_launch(void* const* d_in, const int* in_sizes, int n_in,
                              void* d_out, int out_size) {
    const float* X      = (const float*)d_in[0];   // [512,256,1024]
    const float* logits = (const float*)d_in[1];   // [512,256]
    const float* LQ     = (const float*)d_in[2];   // [16,1024]
    const float* Wq     = (const float*)d_in[3];
    const float* bq     = (const float*)d_in[4];
    const float* Wk     = (const float*)d_in[5];
    // d_in[6] = bk: cancels in softmax, unused
    const float* Wv     = (const float*)d_in[7];
    const float* bv     = (const float*)d_in[8];
    const float* Wo     = (const float*)d_in[9];
    const float* bo     = (const float*)d_in[10];
    float* out = (float*)d_out;

    float *wop, *wvp, *q1p, *b2p;
    __half *q2hp, *w2hp, *yhp;
    cudaGetSymbolAddress((void**)&wop,  g_wo);
    cudaGetSymbolAddress((void**)&wvp,  g_wv);
    cudaGetSymbolAddress((void**)&q1p,  g_q1);
    cudaGetSymbolAddress((void**)&q2hp, g_q2h);
    cudaGetSymbolAddress((void**)&w2hp, g_w2h);
    cudaGetSymbolAddress((void**)&b2p,  g_b2);
    cudaGetSymbolAddress((void**)&yhp,  g_yh);

    // smem opt-in (idempotent)
    cudaFuncSetAttribute((const void*)gemm_cpa<16,64,64,1,4,4,true,true,true,false,true,1>,
                         cudaFuncAttributeMaxDynamicSharedMemorySize, 92160);
    cudaFuncSetAttribute((const void*)gemm_cpa<16,64,64,1,4,4,false,false,false,true,true,1>,
                         cudaFuncAttributeMaxDynamicSharedMemorySize, 92160);
    cudaFuncSetAttribute((const void*)gemm_cpa<64,64,32,2,2,3,false,false,false,true,false,1>,
                         cudaFuncAttributeMaxDynamicSharedMemorySize, 58368);
    cudaFuncSetAttribute((const void*)gemm_h,
                         cudaFuncAttributeMaxDynamicSharedMemorySize, 2 * HSTG * 2);
    cudaFuncSetAttribute((const void*)fused_attn,
                         cudaFuncAttributeMaxDynamicSharedMemorySize, FUSED_SMEM);

    // fork/join infrastructure (per-call; graph replays never re-enter here)
    cudaStream_t s2;
    cudaStreamCreateWithFlags(&s2, cudaStreamNonBlocking);
    cudaEvent_t e1, e2;
    cudaEventCreateWithFlags(&e1, cudaEventDisableTiming);
    cudaEventCreateWithFlags(&e2, cudaEventDisableTiming);

    cudaEventRecord(e1, 0);
    cudaStreamWaitEvent(s2, e1, 0);

    // ---- side branch (stream s2): W2 path, joins before gemm_h ----
    k_round2<<<dim3(1024, 2), 256, 0, s2>>>(wop, Wo, wvp, Wv);
    k_b2<<<4, 256, 0, s2>>>(Wo, bv, bo);
    gemm_cpa<64, 64, 32, 2, 2, 3, false, false, false, true, false, 1><<<dim3(16, 16), 128, 58368, s2>>>(
        wop, wvp, (float*)w2hp, nullptr, 1024, 1024, 1024);
    cudaEventRecord(e2, s2);

    // ---- main branch: q-chain (inline CVT on raw inputs) -> fused attention ----
    // q1 = LQ @ Wq^T + bq    [16,1024], RNA epilogue (tf32-exact out)
    gemm_cpa<16, 64, 64, 1, 4, 4, true, true, true, false, true, 1><<<dim3(16, 1), 128, 92160>>>(
        LQ, Wq, q1p, bq, 16, 1024, 1024);
    // Q2 = q1 @ Wk           [16,1024], fp16 out
    gemm_cpa<16, 64, 64, 1, 4, 4, false, false, false, true, true, 1><<<dim3(16, 1), 128, 92160>>>(
        q1p, Wk, (float*)q2hp, nullptr, 16, 1024, 1024);
    // fused attention (persistent, fp16 mma): Y = softmax(Q2·X^T/32 + logits) @ X
    fused_attn<<<FGRID, 512, FUSED_SMEM>>>(X, logits, yhp);

    // ---- join, then final projection ----
    cudaStreamWaitEvent((cudaStream_t)0, e2, 0);
    gemm_h<<<dim3(8, 64), 128, 2 * HSTG * 2>>>(
        yhp, w2hp, out, b2p, BSZ * SLOTS, HIDDEN, HIDDEN);
}

// round 16
// speedup vs baseline: 1.1181x; 1.0540x over previous
#include <cuda_runtime.h>
#include <cuda_fp16.h>
#include <cstdint>

#define HIDDEN 1024
#define SLOTS 16
#define BSZ 512
#define SEGLEN 256
#define TT 16            // t-tile in fused attention
#define SCALE 0.03125f   // 1/sqrt(1024)

// ---------------- scratch (device globals; no allocation) ----------------
__device__ float  g_wo[HIDDEN * HIDDEN];                  // RNA-rounded Wo
__device__ float  g_wv[HIDDEN * HIDDEN];                  // RNA-rounded Wv
__device__ float  g_qpart[4 * SLOTS * HIDDEN];            // split-K partials
__device__ float  g_q1[SLOTS * HIDDEN];                   // tf32-exact q1
__device__ __half g_q2h[SLOTS * HIDDEN];                  // fp16 Q2
__device__ __half g_w2h[HIDDEN * HIDDEN];                 // fp16 W2 = Wo@Wv
__device__ float  g_b2[HIDDEN];
__device__ __half g_yh[(size_t)BSZ * SLOTS * HIDDEN];     // fp16 Y [b][s][d]

// ---------------- helpers ----------------
__device__ __forceinline__ float tf32r(float x) {
    uint32_t u;
    asm("cvt.rna.tf32.f32 %0, %1;" : "=r"(u) : "f"(x));
    return __uint_as_float(u);
}
__device__ __forceinline__ float4 tf32r4(float4 v) {
    return make_float4(tf32r(v.x), tf32r(v.y), tf32r(v.z), tf32r(v.w));
}
__device__ __forceinline__ uint32_t f2u(float x) { return __float_as_uint(x); }

__device__ __forceinline__ void mma8(float* c, const uint32_t* a, const uint32_t* b) {
    asm volatile(
        "mma.sync.aligned.m16n8k8.row.col.f32.tf32.tf32.f32 "
        "{%0,%1,%2,%3},{%4,%5,%6,%7},{%8,%9},{%0,%1,%2,%3};"
        : "+f"(c[0]), "+f"(c[1]), "+f"(c[2]), "+f"(c[3])
        : "r"(a[0]), "r"(a[1]), "r"(a[2]), "r"(a[3]), "r"(b[0]), "r"(b[1]));
}
__device__ __forceinline__ void mma16h(float* c, const uint32_t* a, const uint32_t* b) {
    asm volatile(
        "mma.sync.aligned.m16n8k16.row.col.f32.f16.f16.f32 "
        "{%0,%1,%2,%3},{%4,%5,%6,%7},{%8,%9},{%0,%1,%2,%3};"
        : "+f"(c[0]), "+f"(c[1]), "+f"(c[2]), "+f"(c[3])
        : "r"(a[0]), "r"(a[1]), "r"(a[2]), "r"(a[3]), "r"(b[0]), "r"(b[1]));
}
__device__ __forceinline__ void ldsm4t(uint32_t& r0, uint32_t& r1, uint32_t& r2, uint32_t& r3,
                                       uint32_t a) {
    asm volatile("ldmatrix.sync.aligned.m8n8.x4.trans.shared.b16 {%0,%1,%2,%3}, [%4];"
                 : "=r"(r0), "=r"(r1), "=r"(r2), "=r"(r3) : "r"(a));
}

__device__ __forceinline__ uint32_t smem_u32(const void* p) {
    uint32_t a;
    asm("{ .reg .u64 t; cvta.to.shared.u64 t, %1; cvt.u32.u64 %0, t; }" : "=r"(a) : "l"(p));
    return a;
}
__device__ __forceinline__ void cpasync16(uint32_t dst, const void* src) {
    asm volatile("cp.async.cg.shared.global [%0], [%1], 16;" :: "r"(dst), "l"(src));
}
#define CP_COMMIT() asm volatile("cp.async.commit_group;")
#define CP_WAIT(n)  asm volatile("cp.async.wait_group %0;" :: "n"(n))

// ---------------- batched RNA round-copy (side branch only) ----------------
__global__ void __launch_bounds__(256) k_round2(
    float* d0, const float* s0, float* d1, const float* s1) {
    const float* s = blockIdx.y ? s1 : s0;
    float* d = blockIdx.y ? d1 : d0;
    int i = blockIdx.x * 256 + threadIdx.x;
    ((float4*)d)[i] = tf32r4(((const float4*)s)[i]);
}

// ---------------- split-K reduce: out = sum_z part[z] (+bias) -> RNA fp32 or fp16 ----------------
template <bool HOUT>
__global__ void __launch_bounds__(256) k_qred(
    const float* __restrict__ part, const float* __restrict__ bias, void* out) {
    int i = blockIdx.x * 256 + threadIdx.x;            // 0 .. 16*1024-1
    float v = (part[i] + part[SLOTS * HIDDEN + i])
            + (part[2 * SLOTS * HIDDEN + i] + part[3 * SLOTS * HIDDEN + i]);
    if (bias) v += bias[i & (HIDDEN - 1)];
    if constexpr (HOUT) ((__half*)out)[i] = __float2half_rn(v);
    else                ((float*)out)[i]  = tf32r(v);
}

// ---------------- multi-stage cp.async tf32 GEMM ----------------
// C[m,n] = sum_k A[m,k] * (BT ? B[n,k] : B[k,n])  (+ bias[n] if BIAS)
// CVT: in-place RNA tf32 convert of the stage before compute (for raw fp32 inputs).
// PART: split-K — blockIdx.z accumulates K/gridDim.z chunk, writes raw fp32 partial.
template <int BM, int BN, int BK, int WM, int WN, int STAGES,
          bool BT, bool BIAS, bool RNA, bool HOUT, bool CVT, bool PART, int MINCTA>
__global__ void __launch_bounds__(WM * WN * 32, MINCTA) gemm_cpa(
    const float* __restrict__ A, const float* __restrict__ B,
    float* __restrict__ C, const float* __restrict__ bias,
    int M, int N, int K)
{
    constexpr int THREADS = WM * WN * 32;
    constexpr int LA = BK + 8;
    constexpr int LB = BN + 8;
    constexpr int ASZ = BM * LA;
    constexpr int BSZE = BT ? BN * LA : BK * LB;
    constexpr int AITER = BM * BK / 4 / THREADS;
    constexpr int BITER = BN * BK / 4 / THREADS;

    extern __shared__ float sm[];

    const int tid  = threadIdx.x;
    const int lane = tid & 31;
    const int warp = tid >> 5;
    const int r  = lane >> 2;
    const int cq = lane & 3;
    const int wm = warp / WN, wn = warp % WN;
    constexpr int WTM = BM / WM, WTN = BN / WN;
    constexpr int MI = WTM / 16, NI = WTN / 8;
    const int mW = wm * WTM, nW = wn * WTN;
    const int m0 = blockIdx.y * BM;
    const int n0 = blockIdx.x * BN;
    const int kchunk = PART ? K / gridDim.z : K;
    const int kbase  = PART ? blockIdx.z * kchunk : 0;

    float acc[MI][NI][4];
    #pragma unroll
    for (int mi = 0; mi < MI; mi++)
        #pragma unroll
        for (int ni = 0; ni < NI; ni++)
            #pragma unroll
            for (int j = 0; j < 4; j++) acc[mi][ni][j] = 0.0f;

    auto issue = [&](int k0, int buf) {
        float* As = sm + buf * (ASZ + BSZE);
        float* Bs = As + ASZ;
        uint32_t ab = smem_u32(As);
        uint32_t bb = smem_u32(Bs);
        #pragma unroll
        for (int i = 0; i < AITER; i++) {
            int idx = i * THREADS + tid;
            int row = idx / (BK / 4), k4 = idx % (BK / 4);
            cpasync16(ab + (row * LA + k4 * 4) * 4,
                      A + (long)(m0 + row) * K + k0 + k4 * 4);
        }
        if constexpr (BT) {
            #pragma unroll
            for (int i = 0; i < BITER; i++) {
                int idx = i * THREADS + tid;
                int row = idx / (BK / 4), k4 = idx % (BK / 4);
                cpasync16(bb + (row * LA + k4 * 4) * 4,
                          B + (long)(n0 + row) * K + k0 + k4 * 4);
            }
        } else {
            #pragma unroll
            for (int i = 0; i < BITER; i++) {
                int idx = i * THREADS + tid;
                int row = idx / (BN / 4), n4 = idx % (BN / 4);
                cpasync16(bb + (row * LB + n4 * 4) * 4,
                          B + (long)(k0 + row) * N + n0 + n4 * 4);
            }
        }
        CP_COMMIT();
    };
    auto compute = [&](int buf) {
        const float* As = sm + buf * (ASZ + BSZE);
        const float* Bs = As + ASZ;
        #pragma unroll
        for (int k8 = 0; k8 < BK / 8; k8++) {
            uint32_t af[MI][4], bf[NI][2];
            #pragma unroll
            for (int mi = 0; mi < MI; mi++) {
                int mr = mW + mi * 16 + r;
                af[mi][0] = f2u(As[mr * LA + k8 * 8 + cq]);
                af[mi][1] = f2u(As[(mr + 8) * LA + k8 * 8 + cq]);
                af[mi][2] = f2u(As[mr * LA + k8 * 8 + cq + 4]);
                af[mi][3] = f2u(As[(mr + 8) * LA + k8 * 8 + cq + 4]);
            }
            #pragma unroll
            for (int ni = 0; ni < NI; ni++) {
                int nc = nW + ni * 8 + r;
                if constexpr (BT) {
                    bf[ni][0] = f2u(Bs[nc * LA + k8 * 8 + cq]);
                    bf[ni][1] = f2u(Bs[nc * LA + k8 * 8 + cq + 4]);
                } else {
                    bf[ni][0] = f2u(Bs[(k8 * 8 + cq) * LB + nc]);
                    bf[ni][1] = f2u(Bs[(k8 * 8 + cq + 4) * LB + nc]);
                }
            }
            #pragma unroll
            for (int mi = 0; mi < MI; mi++)
                #pragma unroll
                for (int ni = 0; ni < NI; ni++)
                    mma8(acc[mi][ni], af[mi], bf[ni]);
        }
    };

    const int NTILES = kchunk / BK;
    #pragma unroll
    for (int s = 0; s < STAGES - 1; s++)
        if (s < NTILES) issue(kbase + s * BK, s);

    for (int t = 0; t < NTILES; t++) {
        if (t + STAGES - 1 < NTILES) {
            issue(kbase + (t + STAGES - 1) * BK, (t + STAGES - 1) % STAGES);
            CP_WAIT(STAGES - 1);
        } else {
            int rem = NTILES - 1 - t;
            if constexpr (STAGES >= 4) { if (rem == 2) CP_WAIT(2); }
            if (rem == 1) CP_WAIT(1);
            else if (rem == 0) CP_WAIT(0);
        }
        __syncthreads();
        if constexpr (CVT) {
            float* base = sm + (t % STAGES) * (ASZ + BSZE);
            constexpr int TOT4 = (ASZ + BSZE) / 4;
            for (int i = tid; i < TOT4; i += THREADS) {
                float4* p = (float4*)base + i;
                *p = tf32r4(*p);
            }
            __syncthreads();
        }
        compute(t % STAGES);
        __syncthreads();
    }

    float* Cg = PART ? C + (long)blockIdx.z * M * N : C;
    #pragma unroll
    for (int mi = 0; mi < MI; mi++) {
        int row = m0 + mW + mi * 16 + r;
        #pragma unroll
        for (int ni = 0; ni < NI; ni++) {
            int col = n0 + nW + ni * 8 + 2 * cq;
            float2 v0 = make_float2(acc[mi][ni][0], acc[mi][ni][1]);
            float2 v1 = make_float2(acc[mi][ni][2], acc[mi][ni][3]);
            if constexpr (BIAS) {
                float b0 = bias[col], b1 = bias[col + 1];
                v0.x += b0; v0.y += b1; v1.x += b0; v1.y += b1;
            }
            if constexpr (HOUT) {
                __half* Ch = (__half*)Cg;
                *(__half2*)(Ch + (long)row * N + col)       = __floats2half2_rn(v0.x, v0.y);
                *(__half2*)(Ch + (long)(row + 8) * N + col) = __floats2half2_rn(v1.x, v1.y);
            } else {
                if constexpr (RNA) {
                    v0.x = tf32r(v0.x); v0.y = tf32r(v0.y);
                    v1.x = tf32r(v1.x); v1.y = tf32r(v1.y);
                }
                *(float2*)(Cg + (long)row * N + col) = v0;
                *(float2*)(Cg + (long)(row + 8) * N + col) = v1;
            }
        }
    }
}

// ---------------- fp16 GEMM for the final projection (cp.async) ----------------
#define HBM 128
#define HBN 128
#define HBK 64
#define HLA 72            // halves per row (BK + 8 pad)
#define HSTG ((HBM + HBN) * HLA)   // halves per stage = 18432 (36864 B)

__global__ void __launch_bounds__(128, 2) gemm_h(
    const __half* __restrict__ A, const __half* __restrict__ B,
    float* __restrict__ C, const float* __restrict__ bias,
    int M, int N, int K)
{
    extern __shared__ __half smh[];

    const int tid  = threadIdx.x;
    const int lane = tid & 31;
    const int warp = tid >> 5;
    const int r  = lane >> 2;
    const int cq = lane & 3;
    const int wm = warp >> 1, wn = warp & 1;
    const int mW = wm * 64, nW = wn * 64;
    const int m0 = blockIdx.y * HBM;
    const int n0 = blockIdx.x * HBN;

    float acc[4][8][4];
    #pragma unroll
    for (int mi = 0; mi < 4; mi++)
        #pragma unroll
        for (int ni = 0; ni < 8; ni++)
            #pragma unroll
            for (int j = 0; j < 4; j++) acc[mi][ni][j] = 0.0f;

    auto issue = [&](int k0, int buf) {
        __half* As = smh + buf * HSTG;
        __half* Bs = As + HBM * HLA;
        uint32_t ab = smem_u32(As);
        uint32_t bb = smem_u32(Bs);
        #pragma unroll
        for (int i = 0; i < 8; i++) {
            int idx = i * 128 + tid;
            int row = idx >> 3, c8 = idx & 7;
            cpasync16(ab + (row * HLA + c8 * 8) * 2,
                      A + (long)(m0 + row) * K + k0 + c8 * 8);
        }
        #pragma unroll
        for (int i = 0; i < 8; i++) {
            int idx = i * 128 + tid;
            int row = idx >> 3, c8 = idx & 7;
            cpasync16(bb + (row * HLA + c8 * 8) * 2,
                      B + (long)(n0 + row) * K + k0 + c8 * 8);
        }
        CP_COMMIT();
    };
    auto compute = [&](int buf) {
        const __half* As = smh + buf * HSTG;
        const __half* Bs = As + HBM * HLA;
        #pragma unroll
        for (int k16 = 0; k16 < 4; k16++) {
            uint32_t af[4][4], bf[8][2];
            #pragma unroll
            for (int mi = 0; mi < 4; mi++) {
                int mr = mW + mi * 16 + r;
                const __half* p0 = As + mr * HLA + k16 * 16 + 2 * cq;
                const __half* p1 = As + (mr + 8) * HLA + k16 * 16 + 2 * cq;
                af[mi][0] = *(const uint32_t*)p0;
                af[mi][1] = *(const uint32_t*)p1;
                af[mi][2] = *(const uint32_t*)(p0 + 8);
                af[mi][3] = *(const uint32_t*)(p1 + 8);
            }
            #pragma unroll
            for (int ni = 0; ni < 8; ni++) {
                int nc = nW + ni * 8 + r;
                const __half* p = Bs + nc * HLA + k16 * 16 + 2 * cq;
                bf[ni][0] = *(const uint32_t*)p;
                bf[ni][1] = *(const uint32_t*)(p + 8);
            }
            #pragma unroll
            for (int mi = 0; mi < 4; mi++)
                #pragma unroll
                for (int ni = 0; ni < 8; ni++)
                    mma16h(acc[mi][ni], af[mi], bf[ni]);
        }
    };

    const int NTILES = K / HBK;   // 16
    issue(0, 0);
    for (int t = 0; t < NTILES; t++) {
        if (t + 1 < NTILES) { issue((t + 1) * HBK, (t + 1) & 1); CP_WAIT(1); }
        else CP_WAIT(0);
        __syncthreads();
        compute(t & 1);
        __syncthreads();
    }

    #pragma unroll
    for (int mi = 0; mi < 4; mi++) {
        int row = m0 + mW + mi * 16 + r;
        #pragma unroll
        for (int ni = 0; ni < 8; ni++) {
            int col = n0 + nW + ni * 8 + 2 * cq;
            float b0 = bias[col], b1 = bias[col + 1];
            *(float2*)(C + (long)row * N + col) =
                make_float2(acc[mi][ni][0] + b0, acc[mi][ni][1] + b1);
            *(float2*)(C + (long)(row + 8) * N + col) =
                make_float2(acc[mi][ni][2] + b0, acc[mi][ni][3] + b1);
        }
    }
}

// ---------------- b2[e] = dot(Wo[e,:], bv) + bo[e]  (exact fp32) ----------------
__global__ void __launch_bounds__(256) k_b2(const float* __restrict__ Wo,
                                            const float* __restrict__ bv,
                                            const float* __restrict__ bo) {
    int e = blockIdx.x * 256 + threadIdx.x;
    const float4* wo = (const float4*)(Wo + (long)e * HIDDEN);
    const float4* bvv = (const float4*)bv;
    float acc = 0.0f;
    #pragma unroll 4
    for (int i = 0; i < HIDDEN / 4; i++) {
        float4 a = wo[i], b = bvv[i];
        acc = fmaf(a.x, b.x, acc); acc = fmaf(a.y, b.y, acc);
        acc = fmaf(a.z, b.z, acc); acc = fmaf(a.w, b.w, acc);
    }
    g_b2[e] = acc + bo[e];
}

// ---------------- fused attention: persistent, fp16 mma, ldmatrix.trans Y ----------------
#define LQ2 1032          // floats per X row in fp32 staging
#define LQH 1048          // halves per X row in fp16 view
#define OFF_X  0
#define OFF_SP (3 * TT * LQ2)
#define OFF_P  (OFF_SP + 16 * 16 * TT)
#define OFF_M  (OFF_P + 16 * 24)
#define OFF_L  (OFF_M + 16)
#define OFF_SC (OFF_L + 16)
#define OFF_LG (OFF_SC + 16)
#define FUSED_SMEM ((OFF_LG + SEGLEN) * 4)
#define FGRID 148

__global__ void __launch_bounds__(512, 1) fused_attn(
    const float* __restrict__ X, const float* __restrict__ logits,
    __half* __restrict__ Y)
{
    extern __shared__ float sm[];
    float*  Xs  = sm + OFF_X;
    float*  Sp  = sm + OFF_SP;
    __half* Psh = (__half*)(sm + OFF_P);      // [16][24] halves
    float*  mS  = sm + OFF_M;
    float*  lS  = sm + OFF_L;
    float*  scS = sm + OFF_SC;
    float*  lgS = sm + OFF_LG;

    const int tid  = threadIdx.x;
    const int lane = tid & 31;
    const int w    = tid >> 5;        // 0..15, d-chunk = [w*64, w*64+64)
    const int r    = lane >> 2;
    const int cq   = lane & 3;

    const int nb = (BSZ - blockIdx.x + FGRID - 1) / FGRID;   // 4 or 3
    const int NG = nb * (SEGLEN / TT);

    auto issueG = [&](int g) {
        int bcur = blockIdx.x + (g >> 4) * FGRID;
        int it   = g & 15;
        const float* src0 = X + (long)bcur * SEGLEN * HIDDEN + (long)it * TT * HIDDEN;
        uint32_t dstb = smem_u32(Xs + (g % 3) * TT * LQ2);
        #pragma unroll
        for (int i = 0; i < 8; i++) {
            int idx = i * 512 + tid;          // 4096 float4 per stage
            int row = idx >> 8, c4 = idx & 255;
            cpasync16(dstb + (row * LQ2 + c4 * 4) * 4, src0 + row * HIDDEN + c4 * 4);
        }
        CP_COMMIT();
    };
    issueG(0); issueG(1);

    // Q2 fp16 fragments in registers
    uint32_t afq[4][4];
    #pragma unroll
    for (int k16 = 0; k16 < 4; k16++) {
        int col = w * 64 + k16 * 16 + 2 * cq;
        const __half* q0 = g_q2h + (long)r * HIDDEN + col;
        const __half* q1 = g_q2h + (long)(r + 8) * HIDDEN + col;
        afq[k16][0] = *(const uint32_t*)q0;
        afq[k16][1] = *(const uint32_t*)q1;
        afq[k16][2] = *(const uint32_t*)(q0 + 8);
        afq[k16][3] = *(const uint32_t*)(q1 + 8);
    }

    float acc[8][4];
    #pragma unroll
    for (int ni = 0; ni < 8; ni++)
        #pragma unroll
        for (int j = 0; j < 4; j++) acc[ni][j] = 0.0f;

    __syncthreads();

    for (int g = 0; g < NG; g++) {
        const int it   = g & 15;
        const int bcur = blockIdx.x + (g >> 4) * FGRID;

        if (g + 2 < NG) { issueG(g + 2); CP_WAIT(2); }
        else if (NG - 1 - g == 1) CP_WAIT(1);
        else CP_WAIT(0);

        float*  XtF = Xs + (g % 3) * TT * LQ2;
        __half* hb  = (__half*)XtF;

        // ---- in-place fp32 -> fp16 convert (each thread reads exactly what it copied) ----
        float4 xv[8];
        #pragma unroll
        for (int i = 0; i < 8; i++) {
            int idx = i * 512 + tid;
            int row = idx >> 8, c4 = idx & 255;
            xv[i] = *(const float4*)(XtF + row * LQ2 + c4 * 4);
        }
        __syncthreads();   // all reads done before overwrite
        #pragma unroll
        for (int i = 0; i < 8; i++) {
            int idx = i * 512 + tid;
            int row = idx >> 8, c4 = idx & 255;
            __half2* dst = (__half2*)(hb + row * LQH + c4 * 4);
            dst[0] = __floats2half2_rn(xv[i].x, xv[i].y);
            dst[1] = __floats2half2_rn(xv[i].z, xv[i].w);
        }
        if (it == 0) {
            if (tid < 256) lgS[tid] = logits[(long)bcur * SEGLEN + tid];
            if (tid < 16) { mS[tid] = -INFINITY; lS[tid] = 0.0f; }
        }
        __syncthreads();   // halves + state visible

        // ---- scores (fp16): warp covers d in [w*64, w*64+64) ----
        {
            float sacc[2][4] = {{0,0,0,0},{0,0,0,0}};
            #pragma unroll
            for (int k16 = 0; k16 < 4; k16++) {
                int kk = w * 64 + k16 * 16;
                uint32_t bf[2][2];
                #pragma unroll
                for (int nt = 0; nt < 2; nt++) {
                    int nc = nt * 8 + r;
                    const __half* p = hb + nc * LQH + kk + 2 * cq;
                    bf[nt][0] = *(const uint32_t*)p;
                    bf[nt][1] = *(const uint32_t*)(p + 8);
                }
                mma16h(sacc[0], afq[k16], bf[0]);
                mma16h(sacc[1], afq[k16], bf[1]);
            }
            #pragma unroll
            for (int nt = 0; nt < 2; nt++) {
                int c0 = nt * 8 + 2 * cq;
                Sp[(w * 16 + r) * TT + c0]         = sacc[nt][0];
                Sp[(w * 16 + r) * TT + c0 + 1]     = sacc[nt][1];
                Sp[(w * 16 + r + 8) * TT + c0]     = sacc[nt][2];
                Sp[(w * 16 + r + 8) * TT + c0 + 1] = sacc[nt][3];
            }
        }
        __syncthreads();

        // ---- online softmax: thread (s = tid>>4, t = tid&15), tid < 256 ----
        if (tid < 256) {
            int s = tid >> 4, t = tid & 15;
            float accs = 0.0f;
            #pragma unroll
            for (int ww = 0; ww < 16; ww++) accs += Sp[(ww * 16 + s) * TT + t];
            float v = accs * SCALE + lgS[it * TT + t];
            float m_t = v;
            #pragma unroll
            for (int o = 8; o; o >>= 1) m_t = fmaxf(m_t, __shfl_xor_sync(0xffffffffu, m_t, o));
            float m_old = mS[s];
            float newm = fmaxf(m_old, m_t);
            float p = expf(v - newm);
            Psh[s * 24 + t] = __float2half_rn(p);
            float sum = p;
            #pragma unroll
            for (int o = 8; o; o >>= 1) sum += __shfl_xor_sync(0xffffffffu, sum, o);
            if (t == 0) {
                float scale = expf(m_old - newm); // 0 on first tile of segment
                lS[s] = lS[s] * scale + sum;
                mS[s] = newm;
                scS[s] = scale;
            }
        }
        __syncthreads();

        // ---- rescale Y acc, then Y += P @ X_tile (ldmatrix.trans B fragments) ----
        {
            float sc0 = scS[r], sc1 = scS[r + 8];
            #pragma unroll
            for (int ni = 0; ni < 8; ni++) {
                acc[ni][0] *= sc0; acc[ni][1] *= sc0;
                acc[ni][2] *= sc1; acc[ni][3] *= sc1;
            }
            uint32_t af[4];
            af[0] = *(const uint32_t*)(Psh + r * 24 + 2 * cq);
            af[1] = *(const uint32_t*)(Psh + (r + 8) * 24 + 2 * cq);
            af[2] = *(const uint32_t*)(Psh + r * 24 + 2 * cq + 8);
            af[3] = *(const uint32_t*)(Psh + (r + 8) * 24 + 2 * cq + 8);
            #pragma unroll
            for (int j = 0; j < 4; j++) {
                int t  = lane & 15;
                int cb = w * 64 + j * 16 + ((lane >> 4) << 3);
                uint32_t b0, b1, b2, b3;
                ldsm4t(b0, b1, b2, b3, smem_u32(hb + t * LQH + cb));
                uint32_t bfA[2] = { b0, b1 };
                uint32_t bfB[2] = { b2, b3 };
                mma16h(acc[2 * j],     af, bfA);
                mma16h(acc[2 * j + 1], af, bfB);
            }
        }

        // ---- segment end: write Y as fp16 (RNE) ----
        if (it == 15) {
            float inv0 = 1.0f / lS[r];
            float inv1 = 1.0f / lS[r + 8];
            __half* Y0 = Y + ((long)bcur * SLOTS + r) * HIDDEN;
            __half* Y1 = Y + ((long)bcur * SLOTS + r + 8) * HIDDEN;
            #pragma unroll
            for (int ni = 0; ni < 8; ni++) {
                int col = w * 64 + ni * 8 + 2 * cq;
                *(__half2*)(Y0 + col) = __floats2half2_rn(acc[ni][0] * inv0, acc[ni][1] * inv0);
                *(__half2*)(Y1 + col) = __floats2half2_rn(acc[ni][2] * inv1, acc[ni][3] * inv1);
            }
        }
        __syncthreads();   // stage halves + Psh/scS/mS/lS protected before next tile
    }
}

// ---------------- launch: fork W2 branch onto a second stream ----------------
extern "C" void kernel_launch(void* const* d_in, const int* in_sizes, int n_in,
                              void* d_out, int out_size) {
    const float* X      = (const float*)d_in[0];   // [512,256,1024]
    const float* logits = (const float*)d_in[1];   // [512,256]
    const float* LQ     = (const float*)d_in[2];   // [16,1024]
    const float* Wq     = (const float*)d_in[3];
    const float* bq     = (const float*)d_in[4];
    const float* Wk     = (const float*)d_in[5];
    // d_in[6] = bk: cancels in softmax, unused
    const float* Wv     = (const float*)d_in[7];
    const float* bv     = (const float*)d_in[8];
    const float* Wo     = (const float*)d_in[9];
    const float* bo     = (const float*)d_in[10];
    float* out = (float*)d_out;

    float *wop, *wvp, *qpp, *q1p, *b2p;
    __half *q2hp, *w2hp, *yhp;
    cudaGetSymbolAddress((void**)&wop,  g_wo);
    cudaGetSymbolAddress((void**)&wvp,  g_wv);
    cudaGetSymbolAddress((void**)&qpp,  g_qpart);
    cudaGetSymbolAddress((void**)&q1p,  g_q1);
    cudaGetSymbolAddress((void**)&q2hp, g_q2h);
    cudaGetSymbolAddress((void**)&w2hp, g_w2h);
    cudaGetSymbolAddress((void**)&b2p,  g_b2);
    cudaGetSymbolAddress((void**)&yhp,  g_yh);

    // smem opt-in (idempotent)
    cudaFuncSetAttribute((const void*)gemm_cpa<16,64,64,1,4,4,true,false,false,false,true,true,1>,
                         cudaFuncAttributeMaxDynamicSharedMemorySize, 92160);
    cudaFuncSetAttribute((const void*)gemm_cpa<16,64,64,1,4,4,false,false,false,false,true,true,1>,
                         cudaFuncAttributeMaxDynamicSharedMemorySize, 92160);
    cudaFuncSetAttribute((const void*)gemm_cpa<64,64,32,2,2,3,false,false,false,true,false,false,1>,
                         cudaFuncAttributeMaxDynamicSharedMemorySize, 58368);
    cudaFuncSetAttribute((const void*)gemm_h,
                         cudaFuncAttributeMaxDynamicSharedMemorySize, 2 * HSTG * 2);
    cudaFuncSetAttribute((const void*)fused_attn,
                         cudaFuncAttributeMaxDynamicSharedMemorySize, FUSED_SMEM);

    // fork/join infrastructure (per-call; graph replays never re-enter here)
    cudaStream_t s2;
    cudaStreamCreateWithFlags(&s2, cudaStreamNonBlocking);
    cudaEvent_t e1, e2;
    cudaEventCreateWithFlags(&e1, cudaEventDisableTiming);
    cudaEventCreateWithFlags(&e2, cudaEventDisableTiming);

    cudaEventRecord(e1, 0);
    cudaStreamWaitEvent(s2, e1, 0);

    // ---- side branch (stream s2): W2 path, joins before gemm_h ----
    k_round2<<<dim3(1024, 2), 256, 0, s2>>>(wop, Wo, wvp, Wv);
    k_b2<<<4, 256, 0, s2>>>(Wo, bv, bo);
    gemm_cpa<64, 64, 32, 2, 2, 3, false, false, false, true, false, false, 1><<<dim3(16, 16), 128, 58368, s2>>>(
        wop, wvp, (float*)w2hp, nullptr, 1024, 1024, 1024);
    cudaEventRecord(e2, s2);

    // ---- main branch: split-K q-chain -> fused attention ----
    // q1 partials: LQ @ Wq^T over 4 K-chunks
    gemm_cpa<16, 64, 64, 1, 4, 4, true, false, false, false, true, true, 1><<<dim3(16, 1, 4), 128, 92160>>>(
        LQ, Wq, qpp, nullptr, 16, 1024, 1024);
    // q1 = sum parts + bq, RNA (tf32-exact)
    k_qred<false><<<64, 256>>>(qpp, bq, q1p);
    // Q2 partials: q1 @ Wk over 4 K-chunks
    gemm_cpa<16, 64, 64, 1, 4, 4, false, false, false, false, true, true, 1><<<dim3(16, 1, 4), 128, 92160>>>(
        q1p, Wk, qpp, nullptr, 16, 1024, 1024);
    // Q2 = fp16(sum parts)
    k_qred<true><<<64, 256>>>(qpp, nullptr, q2hp);
    // fused attention (persistent, fp16 mma): Y = softmax(Q2·X^T/32 + logits) @ X
    fused_attn<<<FGRID, 512, FUSED_SMEM>>>(X, logits, yhp);

    // ---- join, then final projection ----
    cudaStreamWaitEvent((cudaStream_t)0, e2, 0);
    gemm_h<<<dim3(8, 64), 128, 2 * HSTG * 2>>>(
        yhp, w2hp, out, b2p, BSZ * SLOTS, HIDDEN, HIDDEN);
}

// round 17
// speedup vs baseline: 1.1271x; 1.0081x over previous
#include <cuda_runtime.h>
#include <cuda_fp16.h>
#include <cstdint>

#define HIDDEN 1024
#define SLOTS 16
#define BSZ 512
#define SEGLEN 256
#define TT 16            // t-tile in fused attention
#define SCALE 0.03125f   // 1/sqrt(1024)

// ---------------- scratch (device globals; no allocation) ----------------
__device__ float  g_wo[HIDDEN * HIDDEN];                  // RNA-rounded Wo
__device__ float  g_wv[HIDDEN * HIDDEN];                  // RNA-rounded Wv
__device__ float  g_qpart[4 * SLOTS * HIDDEN];            // split-K partials
__device__ float  g_q1[SLOTS * HIDDEN];                   // tf32-exact q1
__device__ __half g_q2h[SLOTS * HIDDEN];                  // fp16 Q2
__device__ __half g_w2h[HIDDEN * HIDDEN];                 // fp16 W2 = Wo@Wv
__device__ float  g_b2[HIDDEN];
__device__ __half g_yh[(size_t)BSZ * SLOTS * HIDDEN];     // fp16 Y [b][s][d]

// ---------------- helpers ----------------
__device__ __forceinline__ float tf32r(float x) {
    uint32_t u;
    asm("cvt.rna.tf32.f32 %0, %1;" : "=r"(u) : "f"(x));
    return __uint_as_float(u);
}
__device__ __forceinline__ float4 tf32r4(float4 v) {
    return make_float4(tf32r(v.x), tf32r(v.y), tf32r(v.z), tf32r(v.w));
}
__device__ __forceinline__ uint32_t f2u(float x) { return __float_as_uint(x); }

__device__ __forceinline__ void mma8(float* c, const uint32_t* a, const uint32_t* b) {
    asm volatile(
        "mma.sync.aligned.m16n8k8.row.col.f32.tf32.tf32.f32 "
        "{%0,%1,%2,%3},{%4,%5,%6,%7},{%8,%9},{%0,%1,%2,%3};"
        : "+f"(c[0]), "+f"(c[1]), "+f"(c[2]), "+f"(c[3])
        : "r"(a[0]), "r"(a[1]), "r"(a[2]), "r"(a[3]), "r"(b[0]), "r"(b[1]));
}
__device__ __forceinline__ void mma16h(float* c, const uint32_t* a, const uint32_t* b) {
    asm volatile(
        "mma.sync.aligned.m16n8k16.row.col.f32.f16.f16.f32 "
        "{%0,%1,%2,%3},{%4,%5,%6,%7},{%8,%9},{%0,%1,%2,%3};"
        : "+f"(c[0]), "+f"(c[1]), "+f"(c[2]), "+f"(c[3])
        : "r"(a[0]), "r"(a[1]), "r"(a[2]), "r"(a[3]), "r"(b[0]), "r"(b[1]));
}
__device__ __forceinline__ void ldsm4t(uint32_t& r0, uint32_t& r1, uint32_t& r2, uint32_t& r3,
                                       uint32_t a) {
    asm volatile("ldmatrix.sync.aligned.m8n8.x4.trans.shared.b16 {%0,%1,%2,%3}, [%4];"
                 : "=r"(r0), "=r"(r1), "=r"(r2), "=r"(r3) : "r"(a));
}

__device__ __forceinline__ uint32_t smem_u32(const void* p) {
    uint32_t a;
    asm("{ .reg .u64 t; cvta.to.shared.u64 t, %1; cvt.u32.u64 %0, t; }" : "=r"(a) : "l"(p));
    return a;
}
__device__ __forceinline__ void cpasync16(uint32_t dst, const void* src) {
    asm volatile("cp.async.cg.shared.global [%0], [%1], 16;" :: "r"(dst), "l"(src));
}
#define CP_COMMIT() asm volatile("cp.async.commit_group;")
#define CP_WAIT(n)  asm volatile("cp.async.wait_group %0;" :: "n"(n))

// ---------------- batched RNA round-copy (side branch only) ----------------
__global__ void __launch_bounds__(256) k_round2(
    float* d0, const float* s0, float* d1, const float* s1) {
    const float* s = blockIdx.y ? s1 : s0;
    float* d = blockIdx.y ? d1 : d0;
    int i = blockIdx.x * 256 + threadIdx.x;
    ((float4*)d)[i] = tf32r4(((const float4*)s)[i]);
}

// ---------------- split-K reduce: out = sum_z part[z] (+bias) -> RNA fp32 or fp16 ----------------
template <bool HOUT>
__global__ void __launch_bounds__(256) k_qred(
    const float* __restrict__ part, const float* __restrict__ bias, void* out) {
    int i = blockIdx.x * 256 + threadIdx.x;            // 0 .. 16*1024-1
    float v = (part[i] + part[SLOTS * HIDDEN + i])
            + (part[2 * SLOTS * HIDDEN + i] + part[3 * SLOTS * HIDDEN + i]);
    if (bias) v += bias[i & (HIDDEN - 1)];
    if constexpr (HOUT) ((__half*)out)[i] = __float2half_rn(v);
    else                ((float*)out)[i]  = tf32r(v);
}

// ---------------- multi-stage cp.async tf32 GEMM ----------------
template <int BM, int BN, int BK, int WM, int WN, int STAGES,
          bool BT, bool BIAS, bool RNA, bool HOUT, bool CVT, bool PART, int MINCTA>
__global__ void __launch_bounds__(WM * WN * 32, MINCTA) gemm_cpa(
    const float* __restrict__ A, const float* __restrict__ B,
    float* __restrict__ C, const float* __restrict__ bias,
    int M, int N, int K)
{
    constexpr int THREADS = WM * WN * 32;
    constexpr int LA = BK + 8;
    constexpr int LB = BN + 8;
    constexpr int ASZ = BM * LA;
    constexpr int BSZE = BT ? BN * LA : BK * LB;
    constexpr int AITER = BM * BK / 4 / THREADS;
    constexpr int BITER = BN * BK / 4 / THREADS;

    extern __shared__ float sm[];

    const int tid  = threadIdx.x;
    const int lane = tid & 31;
    const int warp = tid >> 5;
    const int r  = lane >> 2;
    const int cq = lane & 3;
    const int wm = warp / WN, wn = warp % WN;
    constexpr int WTM = BM / WM, WTN = BN / WN;
    constexpr int MI = WTM / 16, NI = WTN / 8;
    const int mW = wm * WTM, nW = wn * WTN;
    const int m0 = blockIdx.y * BM;
    const int n0 = blockIdx.x * BN;
    const int kchunk = PART ? K / gridDim.z : K;
    const int kbase  = PART ? blockIdx.z * kchunk : 0;

    float acc[MI][NI][4];
    #pragma unroll
    for (int mi = 0; mi < MI; mi++)
        #pragma unroll
        for (int ni = 0; ni < NI; ni++)
            #pragma unroll
            for (int j = 0; j < 4; j++) acc[mi][ni][j] = 0.0f;

    auto issue = [&](int k0, int buf) {
        float* As = sm + buf * (ASZ + BSZE);
        float* Bs = As + ASZ;
        uint32_t ab = smem_u32(As);
        uint32_t bb = smem_u32(Bs);
        #pragma unroll
        for (int i = 0; i < AITER; i++) {
            int idx = i * THREADS + tid;
            int row = idx / (BK / 4), k4 = idx % (BK / 4);
            cpasync16(ab + (row * LA + k4 * 4) * 4,
                      A + (long)(m0 + row) * K + k0 + k4 * 4);
        }
        if constexpr (BT) {
            #pragma unroll
            for (int i = 0; i < BITER; i++) {
                int idx = i * THREADS + tid;
                int row = idx / (BK / 4), k4 = idx % (BK / 4);
                cpasync16(bb + (row * LA + k4 * 4) * 4,
                          B + (long)(n0 + row) * K + k0 + k4 * 4);
            }
        } else {
            #pragma unroll
            for (int i = 0; i < BITER; i++) {
                int idx = i * THREADS + tid;
                int row = idx / (BN / 4), n4 = idx % (BN / 4);
                cpasync16(bb + (row * LB + n4 * 4) * 4,
                          B + (long)(k0 + row) * N + n0 + n4 * 4);
            }
        }
        CP_COMMIT();
    };
    auto compute = [&](int buf) {
        const float* As = sm + buf * (ASZ + BSZE);
        const float* Bs = As + ASZ;
        #pragma unroll
        for (int k8 = 0; k8 < BK / 8; k8++) {
            uint32_t af[MI][4], bf[NI][2];
            #pragma unroll
            for (int mi = 0; mi < MI; mi++) {
                int mr = mW + mi * 16 + r;
                af[mi][0] = f2u(As[mr * LA + k8 * 8 + cq]);
                af[mi][1] = f2u(As[(mr + 8) * LA + k8 * 8 + cq]);
                af[mi][2] = f2u(As[mr * LA + k8 * 8 + cq + 4]);
                af[mi][3] = f2u(As[(mr + 8) * LA + k8 * 8 + cq + 4]);
            }
            #pragma unroll
            for (int ni = 0; ni < NI; ni++) {
                int nc = nW + ni * 8 + r;
                if constexpr (BT) {
                    bf[ni][0] = f2u(Bs[nc * LA + k8 * 8 + cq]);
                    bf[ni][1] = f2u(Bs[nc * LA + k8 * 8 + cq + 4]);
                } else {
                    bf[ni][0] = f2u(Bs[(k8 * 8 + cq) * LB + nc]);
                    bf[ni][1] = f2u(Bs[(k8 * 8 + cq + 4) * LB + nc]);
                }
            }
            #pragma unroll
            for (int mi = 0; mi < MI; mi++)
                #pragma unroll
                for (int ni = 0; ni < NI; ni++)
                    mma8(acc[mi][ni], af[mi], bf[ni]);
        }
    };

    const int NTILES = kchunk / BK;
    #pragma unroll
    for (int s = 0; s < STAGES - 1; s++)
        if (s < NTILES) issue(kbase + s * BK, s);

    for (int t = 0; t < NTILES; t++) {
        if (t + STAGES - 1 < NTILES) {
            issue(kbase + (t + STAGES - 1) * BK, (t + STAGES - 1) % STAGES);
            CP_WAIT(STAGES - 1);
        } else {
            int rem = NTILES - 1 - t;
            if constexpr (STAGES >= 4) { if (rem == 2) CP_WAIT(2); }
            if (rem == 1) CP_WAIT(1);
            else if (rem == 0) CP_WAIT(0);
        }
        __syncthreads();
        if constexpr (CVT) {
            float* base = sm + (t % STAGES) * (ASZ + BSZE);
            constexpr int TOT4 = (ASZ + BSZE) / 4;
            for (int i = tid; i < TOT4; i += THREADS) {
                float4* p = (float4*)base + i;
                *p = tf32r4(*p);
            }
            __syncthreads();
        }
        compute(t % STAGES);
        __syncthreads();
    }

    float* Cg = PART ? C + (long)blockIdx.z * M * N : C;
    #pragma unroll
    for (int mi = 0; mi < MI; mi++) {
        int row = m0 + mW + mi * 16 + r;
        #pragma unroll
        for (int ni = 0; ni < NI; ni++) {
            int col = n0 + nW + ni * 8 + 2 * cq;
            float2 v0 = make_float2(acc[mi][ni][0], acc[mi][ni][1]);
            float2 v1 = make_float2(acc[mi][ni][2], acc[mi][ni][3]);
            if constexpr (BIAS) {
                float b0 = bias[col], b1 = bias[col + 1];
                v0.x += b0; v0.y += b1; v1.x += b0; v1.y += b1;
            }
            if constexpr (HOUT) {
                __half* Ch = (__half*)Cg;
                *(__half2*)(Ch + (long)row * N + col)       = __floats2half2_rn(v0.x, v0.y);
                *(__half2*)(Ch + (long)(row + 8) * N + col) = __floats2half2_rn(v1.x, v1.y);
            } else {
                if constexpr (RNA) {
                    v0.x = tf32r(v0.x); v0.y = tf32r(v0.y);
                    v1.x = tf32r(v1.x); v1.y = tf32r(v1.y);
                }
                *(float2*)(Cg + (long)row * N + col) = v0;
                *(float2*)(Cg + (long)(row + 8) * N + col) = v1;
            }
        }
    }
}

// ---------------- fp16 GEMM for the final projection (cp.async) ----------------
#define HBM 128
#define HBN 128
#define HBK 64
#define HLA 72            // halves per row (BK + 8 pad)
#define HSTG ((HBM + HBN) * HLA)   // halves per stage = 18432 (36864 B)

__global__ void __launch_bounds__(128, 2) gemm_h(
    const __half* __restrict__ A, const __half* __restrict__ B,
    float* __restrict__ C, const float* __restrict__ bias,
    int M, int N, int K)
{
    extern __shared__ __half smh[];

    const int tid  = threadIdx.x;
    const int lane = tid & 31;
    const int warp = tid >> 5;
    const int r  = lane >> 2;
    const int cq = lane & 3;
    const int wm = warp >> 1, wn = warp & 1;
    const int mW = wm * 64, nW = wn * 64;
    const int m0 = blockIdx.y * HBM;
    const int n0 = blockIdx.x * HBN;

    float acc[4][8][4];
    #pragma unroll
    for (int mi = 0; mi < 4; mi++)
        #pragma unroll
        for (int ni = 0; ni < 8; ni++)
            #pragma unroll
            for (int j = 0; j < 4; j++) acc[mi][ni][j] = 0.0f;

    auto issue = [&](int k0, int buf) {
        __half* As = smh + buf * HSTG;
        __half* Bs = As + HBM * HLA;
        uint32_t ab = smem_u32(As);
        uint32_t bb = smem_u32(Bs);
        #pragma unroll
        for (int i = 0; i < 8; i++) {
            int idx = i * 128 + tid;
            int row = idx >> 3, c8 = idx & 7;
            cpasync16(ab + (row * HLA + c8 * 8) * 2,
                      A + (long)(m0 + row) * K + k0 + c8 * 8);
        }
        #pragma unroll
        for (int i = 0; i < 8; i++) {
            int idx = i * 128 + tid;
            int row = idx >> 3, c8 = idx & 7;
            cpasync16(bb + (row * HLA + c8 * 8) * 2,
                      B + (long)(n0 + row) * K + k0 + c8 * 8);
        }
        CP_COMMIT();
    };
    auto compute = [&](int buf) {
        const __half* As = smh + buf * HSTG;
        const __half* Bs = As + HBM * HLA;
        #pragma unroll
        for (int k16 = 0; k16 < 4; k16++) {
            uint32_t af[4][4], bf[8][2];
            #pragma unroll
            for (int mi = 0; mi < 4; mi++) {
                int mr = mW + mi * 16 + r;
                const __half* p0 = As + mr * HLA + k16 * 16 + 2 * cq;
                const __half* p1 = As + (mr + 8) * HLA + k16 * 16 + 2 * cq;
                af[mi][0] = *(const uint32_t*)p0;
                af[mi][1] = *(const uint32_t*)p1;
                af[mi][2] = *(const uint32_t*)(p0 + 8);
                af[mi][3] = *(const uint32_t*)(p1 + 8);
            }
            #pragma unroll
            for (int ni = 0; ni < 8; ni++) {
                int nc = nW + ni * 8 + r;
                const __half* p = Bs + nc * HLA + k16 * 16 + 2 * cq;
                bf[ni][0] = *(const uint32_t*)p;
                bf[ni][1] = *(const uint32_t*)(p + 8);
            }
            #pragma unroll
            for (int mi = 0; mi < 4; mi++)
                #pragma unroll
                for (int ni = 0; ni < 8; ni++)
                    mma16h(acc[mi][ni], af[mi], bf[ni]);
        }
    };

    const int NTILES = K / HBK;   // 16
    issue(0, 0);
    for (int t = 0; t < NTILES; t++) {
        if (t + 1 < NTILES) { issue((t + 1) * HBK, (t + 1) & 1); CP_WAIT(1); }
        else CP_WAIT(0);
        __syncthreads();
        compute(t & 1);
        __syncthreads();
    }

    #pragma unroll
    for (int mi = 0; mi < 4; mi++) {
        int row = m0 + mW + mi * 16 + r;
        #pragma unroll
        for (int ni = 0; ni < 8; ni++) {
            int col = n0 + nW + ni * 8 + 2 * cq;
            float b0 = bias[col], b1 = bias[col + 1];
            *(float2*)(C + (long)row * N + col) =
                make_float2(acc[mi][ni][0] + b0, acc[mi][ni][1] + b1);
            *(float2*)(C + (long)(row + 8) * N + col) =
                make_float2(acc[mi][ni][2] + b0, acc[mi][ni][3] + b1);
        }
    }
}

// ---------------- b2[e] = dot(Wo[e,:], bv) + bo[e]  (exact fp32) ----------------
__global__ void __launch_bounds__(256) k_b2(const float* __restrict__ Wo,
                                            const float* __restrict__ bv,
                                            const float* __restrict__ bo) {
    int e = blockIdx.x * 256 + threadIdx.x;
    const float4* wo = (const float4*)(Wo + (long)e * HIDDEN);
    const float4* bvv = (const float4*)bv;
    float acc = 0.0f;
    #pragma unroll 4
    for (int i = 0; i < HIDDEN / 4; i++) {
        float4 a = wo[i], b = bvv[i];
        acc = fmaf(a.x, b.x, acc); acc = fmaf(a.y, b.y, acc);
        acc = fmaf(a.z, b.z, acc); acc = fmaf(a.w, b.w, acc);
    }
    g_b2[e] = acc + bo[e];
}

// ---------------- fused attention: LDG register prefetch + direct fp16 staging ----------------
// smem: XH[2][16][LQH] fp16 | Sp[16*16*16] f32 | Psh[16*24] f16 | mS/lS/scS[16] | lgS[256]
#define LQH 1048
#define XH_BYTES (2 * TT * LQH * 2)              // 67072
#define SP_OFF   XH_BYTES
#define PSH_OFF  (SP_OFF + 16 * 16 * TT * 4)     // 83456
#define MS_OFF   (PSH_OFF + 16 * 24 * 2 + 0)     // 84224
#define LS_OFF   (MS_OFF + 64)
#define SCS_OFF  (LS_OFF + 64)
#define LGS_OFF  (SCS_OFF + 64)
#define FUSED_SMEM (LGS_OFF + SEGLEN * 4)        // 85440
#define FGRID 148

__global__ void __launch_bounds__(512, 1) fused_attn(
    const float* __restrict__ X, const float* __restrict__ logits,
    __half* __restrict__ Y)
{
    extern __shared__ __align__(16) unsigned char smraw[];
    __half* XH  = (__half*)smraw;
    float*  Sp  = (float*)(smraw + SP_OFF);
    __half* Psh = (__half*)(smraw + PSH_OFF);
    float*  mS  = (float*)(smraw + MS_OFF);
    float*  lS  = (float*)(smraw + LS_OFF);
    float*  scS = (float*)(smraw + SCS_OFF);
    float*  lgS = (float*)(smraw + LGS_OFF);

    const int tid  = threadIdx.x;
    const int lane = tid & 31;
    const int w    = tid >> 5;        // 0..15, d-chunk = [w*64, w*64+64)
    const int r    = lane >> 2;
    const int cq   = lane & 3;

    const int nb = (BSZ - blockIdx.x + FGRID - 1) / FGRID;   // 4 or 3
    const int NG = nb * (SEGLEN / TT);

    const int ld_row = tid >> 8;          // this thread's fixed (row-base, col) slots
    const int ld_c4  = tid & 255;

    float4 xv[8];
    auto ldgX = [&](int g) {
        int bcur = blockIdx.x + (g >> 4) * FGRID;
        int it   = g & 15;
        const float* src0 = X + (long)bcur * SEGLEN * HIDDEN + (long)it * TT * HIDDEN;
        #pragma unroll
        for (int i = 0; i < 8; i++)
            xv[i] = *(const float4*)(src0 + (i * 2 + ld_row) * HIDDEN + ld_c4 * 4);
    };
    auto stsX = [&](int g) {
        __half* dst = XH + (g & 1) * TT * LQH;
        #pragma unroll
        for (int i = 0; i < 8; i++) {
            __half2* d2 = (__half2*)(dst + (i * 2 + ld_row) * LQH + ld_c4 * 4);
            d2[0] = __floats2half2_rn(xv[i].x, xv[i].y);
            d2[1] = __floats2half2_rn(xv[i].z, xv[i].w);
        }
    };

    // prologue: tile 0 staged, tile 1 in registers
    ldgX(0);
    stsX(0);
    ldgX(1);

    // Q2 fp16 fragments in registers
    uint32_t afq[4][4];
    #pragma unroll
    for (int k16 = 0; k16 < 4; k16++) {
        int col = w * 64 + k16 * 16 + 2 * cq;
        const __half* q0 = g_q2h + (long)r * HIDDEN + col;
        const __half* q1 = g_q2h + (long)(r + 8) * HIDDEN + col;
        afq[k16][0] = *(const uint32_t*)q0;
        afq[k16][1] = *(const uint32_t*)q1;
        afq[k16][2] = *(const uint32_t*)(q0 + 8);
        afq[k16][3] = *(const uint32_t*)(q1 + 8);
    }

    float acc[8][4];
    #pragma unroll
    for (int ni = 0; ni < 8; ni++)
        #pragma unroll
        for (int j = 0; j < 4; j++) acc[ni][j] = 0.0f;

    __syncthreads();   // XH buf0 visible

    for (int g = 0; g < NG; g++) {
        const int it   = g & 15;
        const int bcur = blockIdx.x + (g >> 4) * FGRID;
        __half* hb = XH + (g & 1) * TT * LQH;

        // segment start: logits + softmax state (read after the next barrier)
        if (it == 0) {
            if (tid < 256) lgS[tid] = logits[(long)bcur * SEGLEN + tid];
            if (tid < 16) { mS[tid] = -INFINITY; lS[tid] = 0.0f; }
        }

        // ---- scores (fp16): warp covers d in [w*64, w*64+64) ----
        {
            float sacc[2][4] = {{0,0,0,0},{0,0,0,0}};
            #pragma unroll
            for (int k16 = 0; k16 < 4; k16++) {
                int kk = w * 64 + k16 * 16;
                uint32_t bf[2][2];
                #pragma unroll
                for (int nt = 0; nt < 2; nt++) {
                    int nc = nt * 8 + r;
                    const __half* p = hb + nc * LQH + kk + 2 * cq;
                    bf[nt][0] = *(const uint32_t*)p;
                    bf[nt][1] = *(const uint32_t*)(p + 8);
                }
                mma16h(sacc[0], afq[k16], bf[0]);
                mma16h(sacc[1], afq[k16], bf[1]);
            }
            #pragma unroll
            for (int nt = 0; nt < 2; nt++) {
                int c0 = nt * 8 + 2 * cq;
                Sp[(w * 16 + r) * TT + c0]         = sacc[nt][0];
                Sp[(w * 16 + r) * TT + c0 + 1]     = sacc[nt][1];
                Sp[(w * 16 + r + 8) * TT + c0]     = sacc[nt][2];
                Sp[(w * 16 + r + 8) * TT + c0 + 1] = sacc[nt][3];
            }
        }
        __syncthreads();

        // ---- online softmax: thread (s = tid>>4, t = tid&15), tid < 256 ----
        if (tid < 256) {
            int s = tid >> 4, t = tid & 15;
            float accs = 0.0f;
            #pragma unroll
            for (int ww = 0; ww < 16; ww++) accs += Sp[(ww * 16 + s) * TT + t];
            float v = accs * SCALE + lgS[it * TT + t];
            float m_t = v;
            #pragma unroll
            for (int o = 8; o; o >>= 1) m_t = fmaxf(m_t, __shfl_xor_sync(0xffffffffu, m_t, o));
            float m_old = mS[s];
            float newm = fmaxf(m_old, m_t);
            float p = expf(v - newm);
            Psh[s * 24 + t] = __float2half_rn(p);
            float sum = p;
            #pragma unroll
            for (int o = 8; o; o >>= 1) sum += __shfl_xor_sync(0xffffffffu, sum, o);
            if (t == 0) {
                float scale = expf(m_old - newm); // 0 on first tile of segment
                lS[s] = lS[s] * scale + sum;
                mS[s] = newm;
                scS[s] = scale;
            }
        }
        __syncthreads();

        // ---- rescale Y acc, then Y += P @ X_tile (ldmatrix.trans B fragments) ----
        {
            float sc0 = scS[r], sc1 = scS[r + 8];
            #pragma unroll
            for (int ni = 0; ni < 8; ni++) {
                acc[ni][0] *= sc0; acc[ni][1] *= sc0;
                acc[ni][2] *= sc1; acc[ni][3] *= sc1;
            }
            uint32_t af[4];
            af[0] = *(const uint32_t*)(Psh + r * 24 + 2 * cq);
            af[1] = *(const uint32_t*)(Psh + (r + 8) * 24 + 2 * cq);
            af[2] = *(const uint32_t*)(Psh + r * 24 + 2 * cq + 8);
            af[3] = *(const uint32_t*)(Psh + (r + 8) * 24 + 2 * cq + 8);
            #pragma unroll
            for (int j = 0; j < 4; j++) {
                int t  = lane & 15;
                int cb = w * 64 + j * 16 + ((lane >> 4) << 3);
                uint32_t b0, b1, b2, b3;
                ldsm4t(b0, b1, b2, b3, smem_u32(hb + t * LQH + cb));
                uint32_t bfA[2] = { b0, b1 };
                uint32_t bfB[2] = { b2, b3 };
                mma16h(acc[2 * j],     af, bfA);
                mma16h(acc[2 * j + 1], af, bfB);
            }
        }

        // ---- segment end: write Y as fp16 (RNE) ----
        if (it == 15) {
            float inv0 = 1.0f / lS[r];
            float inv1 = 1.0f / lS[r + 8];
            __half* Y0 = Y + ((long)bcur * SLOTS + r) * HIDDEN;
            __half* Y1 = Y + ((long)bcur * SLOTS + r + 8) * HIDDEN;
            #pragma unroll
            for (int ni = 0; ni < 8; ni++) {
                int col = w * 64 + ni * 8 + 2 * cq;
                *(__half2*)(Y0 + col) = __floats2half2_rn(acc[ni][0] * inv0, acc[ni][1] * inv0);
                *(__half2*)(Y1 + col) = __floats2half2_rn(acc[ni][2] * inv1, acc[ni][3] * inv1);
            }
        }

        // ---- stage tile g+1 (held in xv) into the other buffer; prefetch g+2 ----
        if (g + 1 < NG) {
            stsX(g + 1);            // writes buf (g+1)&1: its last reader (tile g-1) is done
            if (g + 2 < NG) ldgX(g + 2);
        }
        __syncthreads();            // new stage + Sp/Psh/scS/mS/lS protected
    }
}

// ---------------- launch: fork W2 branch onto a second stream ----------------
extern "C" void kernel_launch(void* const* d_in, const int* in_sizes, int n_in,
                              void* d_out, int out_size) {
    const float* X      = (const float*)d_in[0];   // [512,256,1024]
    const float* logits = (const float*)d_in[1];   // [512,256]
    const float* LQ     = (const float*)d_in[2];   // [16,1024]
    const float* Wq     = (const float*)d_in[3];
    const float* bq     = (const float*)d_in[4];
    const float* Wk     = (const float*)d_in[5];
    // d_in[6] = bk: cancels in softmax, unused
    const float* Wv     = (const float*)d_in[7];
    const float* bv     = (const float*)d_in[8];
    const float* Wo     = (const float*)d_in[9];
    const float* bo     = (const float*)d_in[10];
    float* out = (float*)d_out;

    float *wop, *wvp, *qpp, *q1p, *b2p;
    __half *q2hp, *w2hp, *yhp;
    cudaGetSymbolAddress((void**)&wop,  g_wo);
    cudaGetSymbolAddress((void**)&wvp,  g_wv);
    cudaGetSymbolAddress((void**)&qpp,  g_qpart);
    cudaGetSymbolAddress((void**)&q1p,  g_q1);
    cudaGetSymbolAddress((void**)&q2hp, g_q2h);
    cudaGetSymbolAddress((void**)&w2hp, g_w2h);
    cudaGetSymbolAddress((void**)&b2p,  g_b2);
    cudaGetSymbolAddress((void**)&yhp,  g_yh);

    // smem opt-in (idempotent)
    cudaFuncSetAttribute((const void*)gemm_cpa<16,64,64,1,4,4,true,false,false,false,true,true,1>,
                         cudaFuncAttributeMaxDynamicSharedMemorySize, 92160);
    cudaFuncSetAttribute((const void*)gemm_cpa<16,64,64,1,4,4,false,false,false,false,true,true,1>,
                         cudaFuncAttributeMaxDynamicSharedMemorySize, 92160);
    cudaFuncSetAttribute((const void*)gemm_cpa<64,64,32,2,2,3,false,false,false,true,false,false,1>,
                         cudaFuncAttributeMaxDynamicSharedMemorySize, 58368);
    cudaFuncSetAttribute((const void*)gemm_h,
                         cudaFuncAttributeMaxDynamicSharedMemorySize, 2 * HSTG * 2);
    cudaFuncSetAttribute((const void*)fused_attn,
                         cudaFuncAttributeMaxDynamicSharedMemorySize, FUSED_SMEM);

    // fork/join infrastructure (per-call; graph replays never re-enter here)
    cudaStream_t s2;
    cudaStreamCreateWithFlags(&s2, cudaStreamNonBlocking);
    cudaEvent_t e1, e2;
    cudaEventCreateWithFlags(&e1, cudaEventDisableTiming);
    cudaEventCreateWithFlags(&e2, cudaEventDisableTiming);

    cudaEventRecord(e1, 0);
    cudaStreamWaitEvent(s2, e1, 0);

    // ---- side branch (stream s2): W2 path, joins before gemm_h ----
    k_round2<<<dim3(1024, 2), 256, 0, s2>>>(wop, Wo, wvp, Wv);
    k_b2<<<4, 256, 0, s2>>>(Wo, bv, bo);
    gemm_cpa<64, 64, 32, 2, 2, 3, false, false, false, true, false, false, 1><<<dim3(16, 16), 128, 58368, s2>>>(
        wop, wvp, (float*)w2hp, nullptr, 1024, 1024, 1024);
    cudaEventRecord(e2, s2);

    // ---- main branch: split-K q-chain -> fused attention ----
    gemm_cpa<16, 64, 64, 1, 4, 4, true, false, false, false, true, true, 1><<<dim3(16, 1, 4), 128, 92160>>>(
        LQ, Wq, qpp, nullptr, 16, 1024, 1024);
    k_qred<false><<<64, 256>>>(qpp, bq, q1p);
    gemm_cpa<16, 64, 64, 1, 4, 4, false, false, false, false, true, true, 1><<<dim3(16, 1, 4), 128, 92160>>>(
        q1p, Wk, qpp, nullptr, 16, 1024, 1024);
    k_qred<true><<<64, 256>>>(qpp, nullptr, q2hp);
    // fused attention (persistent, LDG prefetch + fp16 staging)
    fused_attn<<<FGRID, 512, FUSED_SMEM>>>(X, logits, yhp);

    // ---- join, then final projection ----
    cudaStreamWaitEvent((cudaStream_t)0, e2, 0);
    gemm_h<<<dim3(8, 64), 128, 2 * HSTG * 2>>>(
        yhp, w2hp, out, b2p, BSZ * SLOTS, HIDDEN, HIDDEN);
}